// round 5
// baseline (speedup 1.0000x reference)
#include <cuda_runtime.h>
#include <math.h>

#define BATCH 4
#define SEQ   2048
#define DIM   128
#define ROWS  (BATCH*SEQ)   // 8192

typedef unsigned long long ull;
typedef unsigned int uint32;

// ---------------- scratch (no allocation allowed) ----------------
__device__ float g_q[ROWS*DIM];       // tf32-rounded, row-major [token][128]
__device__ float g_k[ROWS*DIM];       // tf32-rounded
__device__ float g_vt[ROWS*DIM];      // tf32-rounded, TRANSPOSED: [b][d=128][token=2048]
__device__ float g_u[ROWS*2*DIM];     // full f32
__device__ float g_sattn[ROWS*DIM];
__device__ float g_pattn[ROWS*DIM];
__device__ float g_g[ROWS*2*DIM];

__device__ __forceinline__ float silu_f(float v) {
    return v * (1.f / (1.f + __expf(-v)));
}
__device__ __forceinline__ uint32 tf32_of(float f) {
    uint32 u; asm("cvt.rna.tf32.f32 %0, %1;" : "=r"(u) : "f"(f)); return u;
}
__device__ __forceinline__ float tf32f(float f) { return __uint_as_float(tf32_of(f)); }
__device__ __forceinline__ uint32 fb(float f) { return __float_as_uint(f); }
__device__ __forceinline__ uint32 smem_u32(const void* p) {
    return (uint32)__cvta_generic_to_shared(p);
}

__device__ __forceinline__ void mma_tf32(float4& d, uint32 a0, uint32 a1, uint32 a2, uint32 a3,
                                         uint32 b0, uint32 b1) {
    asm volatile(
        "mma.sync.aligned.m16n8k8.row.col.f32.tf32.tf32.f32 "
        "{%0,%1,%2,%3}, {%4,%5,%6,%7}, {%8,%9}, {%0,%1,%2,%3};"
        : "+f"(d.x), "+f"(d.y), "+f"(d.z), "+f"(d.w)
        : "r"(a0), "r"(a1), "r"(a2), "r"(a3), "r"(b0), "r"(b1));
}
__device__ __forceinline__ void ldsm_x4(uint32& r0, uint32& r1, uint32& r2, uint32& r3, uint32 addr) {
    asm volatile("ldmatrix.sync.aligned.m8n8.x4.shared.b16 {%0,%1,%2,%3}, [%4];"
        : "=r"(r0), "=r"(r1), "=r"(r2), "=r"(r3) : "r"(addr));
}
__device__ __forceinline__ void ldsm_x2(uint32& r0, uint32& r1, uint32 addr) {
    asm volatile("ldmatrix.sync.aligned.m8n8.x2.shared.b16 {%0,%1}, [%2];"
        : "=r"(r0), "=r"(r1) : "r"(addr));
}
__device__ __forceinline__ void cp16(uint32 dst, const float* src) {
    asm volatile("cp.async.ca.shared.global [%0], [%1], 16;" :: "r"(dst), "l"(src));
}
#define CP_COMMIT() asm volatile("cp.async.commit_group;")
#define CP_WAIT1()  asm volatile("cp.async.wait_group 1;")
#define CP_WAIT0()  asm volatile("cp.async.wait_group 0;")

// ---------------- kernel 1: fused q/k/v/u projections (tf32 mma) ----------------
// grid (5, 128). seg 0=q, 1=k, 2=v(transposed out), 3/4=u halves.
__global__ __launch_bounds__(256) void proj_kernel(
    const float* __restrict__ x,
    const float* __restrict__ Wq, const float* __restrict__ bq,
    const float* __restrict__ Wk, const float* __restrict__ bk,
    const float* __restrict__ Wv, const float* __restrict__ bv,
    const float* __restrict__ Wu, const float* __restrict__ bu)
{
    __shared__ float xs[64][36];
    __shared__ float ws[32][136];

    const int seg = blockIdx.x;
    const int r0  = blockIdx.y * 64;

    const float* W; const float* bias; int ldw, c0;
    if (seg == 0)      { W = Wq; bias = bq; ldw = 128; c0 = 0; }
    else if (seg == 1) { W = Wk; bias = bk; ldw = 128; c0 = 0; }
    else if (seg == 2) { W = Wv; bias = bv; ldw = 128; c0 = 0; }
    else               { W = Wu; bias = bu; ldw = 256; c0 = (seg - 3) * 128; }

    const int t = threadIdx.x;
    const int w = t >> 5, lane = t & 31;
    const int wm = w & 3, wn = w >> 2;
    const int g = lane >> 2, tg = lane & 3;

    float4 acc[8];
    #pragma unroll
    for (int j = 0; j < 8; j++) acc[j] = make_float4(0.f, 0.f, 0.f, 0.f);

    for (int kc = 0; kc < 128; kc += 32) {
        #pragma unroll
        for (int i = t*4; i < 64*32; i += 256*4) {
            int rr = i >> 5, cc = i & 31;
            float4 v4 = *(const float4*)&x[(r0 + rr) * 128 + kc + cc];
            xs[rr][cc+0] = tf32f(v4.x); xs[rr][cc+1] = tf32f(v4.y);
            xs[rr][cc+2] = tf32f(v4.z); xs[rr][cc+3] = tf32f(v4.w);
        }
        #pragma unroll
        for (int i = t*4; i < 32*128; i += 256*4) {
            int rr = i >> 7, cc = i & 127;
            float4 v4 = *(const float4*)&W[(kc + rr) * ldw + c0 + cc];
            ws[rr][cc+0] = tf32f(v4.x); ws[rr][cc+1] = tf32f(v4.y);
            ws[rr][cc+2] = tf32f(v4.z); ws[rr][cc+3] = tf32f(v4.w);
        }
        __syncthreads();

        #pragma unroll
        for (int kk = 0; kk < 32; kk += 8) {
            uint32 a0 = fb(xs[wm*16 + g    ][kk + tg    ]);
            uint32 a1 = fb(xs[wm*16 + g + 8][kk + tg    ]);
            uint32 a2 = fb(xs[wm*16 + g    ][kk + tg + 4]);
            uint32 a3 = fb(xs[wm*16 + g + 8][kk + tg + 4]);
            #pragma unroll
            for (int j = 0; j < 8; j++) {
                uint32 b0 = fb(ws[kk + tg    ][wn*64 + j*8 + g]);
                uint32 b1 = fb(ws[kk + tg + 4][wn*64 + j*8 + g]);
                mma_tf32(acc[j], a0, a1, a2, a3, b0, b1);
            }
        }
        __syncthreads();
    }

    if (seg == 2) {
        // v: transposed tf32 store into g_vt[b][d][token]
        const int bb = r0 >> 11;
        const int tok = (r0 & 2047) + wm*16 + g;
        #pragma unroll
        for (int j = 0; j < 8; j++) {
            int col = wn*64 + j*8 + 2*tg;
            float b0v = bias[col], b1v = bias[col + 1];
            float v00 = tf32f(silu_f(acc[j].x + b0v));
            float v01 = tf32f(silu_f(acc[j].y + b1v));
            float v10 = tf32f(silu_f(acc[j].z + b0v));
            float v11 = tf32f(silu_f(acc[j].w + b1v));
            float* p0 = &g_vt[(bb*128 + col) * SEQ + tok];
            p0[0] = v00; p0[8] = v10;
            float* p1 = p0 + SEQ;
            p1[0] = v01; p1[8] = v11;
        }
    } else {
        float* out = (seg == 0) ? g_q : (seg == 1) ? g_k : g_u;
        bool act = (seg <= 1);
        #pragma unroll
        for (int j = 0; j < 8; j++) {
            int col = c0 + wn*64 + j*8 + 2*tg;
            float b0v = bias[col], b1v = bias[col + 1];
            int row0 = r0 + wm*16 + g;
            float v00 = acc[j].x + b0v, v01 = acc[j].y + b1v;
            float v10 = acc[j].z + b0v, v11 = acc[j].w + b1v;
            if (act) {
                v00 = tf32f(silu_f(v00)); v01 = tf32f(silu_f(v01));
                v10 = tf32f(silu_f(v10)); v11 = tf32f(silu_f(v11));
            }
            *(float2*)&out[row0 * ldw + col]       = make_float2(v00, v01);
            *(float2*)&out[(row0 + 8) * ldw + col] = make_float2(v10, v11);
        }
    }
}

// ---------------- kernel 2: causal attention (ldmatrix + cp.async pipeline) ----------------
// grid (16, 16): m-tile 128 rows (reversed order), (b,h). 8 warps = 4m x 2n.
// dyn smem: qs 128x36 | ks 2x64x36 | vts 2x32x68 | ss 128x68  = 89088 B
#define ATTN_SMEM 89088
__global__ __launch_bounds__(256, 2) void attn_kernel()
{
    extern __shared__ float sm[];
    float (*qs)[36]  = (float(*)[36])sm;                 // 128 rows
    float (*ks)[36]  = (float(*)[36])(sm + 4608);        // 2*64 rows
    float (*vts)[68] = (float(*)[68])(sm + 9216);        // 2*32 rows
    float (*ss)[68]  = (float(*)[68])(sm + 13568);       // 128 rows

    const int tile = (int)gridDim.x - 1 - (int)blockIdx.x;   // big tiles first
    const int n0 = tile * 128;
    const int b = blockIdx.y >> 2, h = blockIdx.y & 3;
    const int t = threadIdx.x, w = t >> 5, lane = t & 31;
    const int wm = w & 3, wn = w >> 2;
    const int g = lane >> 2, tg = lane & 3;
    const float scale = 0.17677669529663687f;  // 1/sqrt(32)

    const float* qp  = g_q  + (b*SEQ + n0)*128 + h*32;
    const float* kp  = g_k  + (b*SEQ)*128 + h*32;
    const float* vtp = g_vt + (b*128 + h*32)*SEQ;

    const uint32 qs_u = smem_u32(&qs[0][0]);
    const uint32 ks_u = smem_u32(&ks[0][0]);
    const uint32 vt_u = smem_u32(&vts[0][0]);
    const uint32 ss_u = smem_u32(&ss[0][0]);

    // ldmatrix lane-address components
    const int lrow = lane & 7;
    const int sel4 = lane >> 3;
    const int a_ro = ((sel4 & 1) << 3) + lrow;     // row-in-16 for x4
    const int a_co = (sel4 & 2) ? 4 : 0;           // k-offset for x4
    const int l16  = lane & 15;
    const int b_ro = l16 & 7;
    const int b_co = (l16 >> 3) << 2;

    // q tile: 128 rows x 32 floats
    #pragma unroll
    for (int c = t; c < 1024; c += 256) {
        int r = c >> 3, s = (c & 7) << 2;
        cp16(qs_u + (r*36 + s)*4, qp + r*128 + s);
    }
    // first k/vt tile
    {
        #pragma unroll
        for (int c = t; c < 512; c += 256) {
            int r = c >> 3, s = (c & 7) << 2;
            cp16(ks_u + (r*36 + s)*4, kp + r*128 + s);
        }
        #pragma unroll
        for (int c = t; c < 512; c += 256) {
            int r = c >> 4, s = (c & 15) << 2;
            cp16(vt_u + (r*68 + s)*4, vtp + r*SEQ + s);
        }
    }
    CP_COMMIT();

    float4 acc2[2][2];
    #pragma unroll
    for (int mi = 0; mi < 2; mi++)
        #pragma unroll
        for (int j = 0; j < 2; j++) acc2[mi][j] = make_float4(0.f, 0.f, 0.f, 0.f);

    const uint32 qa0 = qs_u + ((wm*32 + a_ro)*36 + a_co)*4;
    const uint32 qa1 = qa0 + 16*36*4;
    const uint32 sa0 = ss_u + ((wm*32 + a_ro)*68 + a_co)*4;
    const uint32 sa1 = sa0 + 16*68*4;

    const int iters = 2*tile + 2;
    for (int it = 0; it < iters; ++it) {
        const int m0 = it * 64;
        const int buf = it & 1;
        if (it + 1 < iters) {
            const int m1 = m0 + 64, nb = buf ^ 1;
            #pragma unroll
            for (int c = t; c < 512; c += 256) {
                int r = c >> 3, s = (c & 7) << 2;
                cp16(ks_u + ((nb*64 + r)*36 + s)*4, kp + (m1 + r)*128 + s);
            }
            #pragma unroll
            for (int c = t; c < 512; c += 256) {
                int r = c >> 4, s = (c & 15) << 2;
                cp16(vt_u + ((nb*32 + r)*68 + s)*4, vtp + r*SEQ + m1 + s);
            }
            CP_COMMIT();
            CP_WAIT1();
        } else {
            CP_WAIT0();
        }
        __syncthreads();

        // ---- stage 1: scores m128 x n64 (warp m32 x n32)
        float4 sc[2][4];
        #pragma unroll
        for (int mi = 0; mi < 2; mi++)
            #pragma unroll
            for (int j = 0; j < 4; j++) sc[mi][j] = make_float4(0.f, 0.f, 0.f, 0.f);

        const uint32 kb = ks_u + (uint32)buf*64*36*4 + ((wn*32 + b_ro)*36 + b_co)*4;
        #pragma unroll
        for (int kk = 0; kk < 32; kk += 8) {
            uint32 A0[4], A1[4];
            ldsm_x4(A0[0], A0[1], A0[2], A0[3], qa0 + kk*4);
            ldsm_x4(A1[0], A1[1], A1[2], A1[3], qa1 + kk*4);
            #pragma unroll
            for (int j = 0; j < 4; j++) {
                uint32 b0, b1;
                ldsm_x2(b0, b1, kb + (j*8*36 + kk)*4);
                mma_tf32(sc[0][j], A0[0], A0[1], A0[2], A0[3], b0, b1);
                mma_tf32(sc[1][j], A1[0], A1[1], A1[2], A1[3], b0, b1);
            }
        }

        // mask + square + silu -> ss
        #pragma unroll
        for (int mi = 0; mi < 2; mi++) {
            const int lr = wm*32 + mi*16 + g;
            const int nrow0 = n0 + lr, nrow1 = nrow0 + 8;
            #pragma unroll
            for (int j = 0; j < 4; j++) {
                const int lc = wn*32 + j*8 + 2*tg;
                const int c0 = m0 + lc;
                float s;
                s = sc[mi][j].x * scale; s = (c0     <= nrow0) ? s*s : 0.f; float w00 = tf32f(silu_f(s));
                s = sc[mi][j].y * scale; s = (c0 + 1 <= nrow0) ? s*s : 0.f; float w01 = tf32f(silu_f(s));
                s = sc[mi][j].z * scale; s = (c0     <= nrow1) ? s*s : 0.f; float w10 = tf32f(silu_f(s));
                s = sc[mi][j].w * scale; s = (c0 + 1 <= nrow1) ? s*s : 0.f; float w11 = tf32f(silu_f(s));
                *(float2*)&ss[lr    ][lc] = make_float2(w00, w01);
                *(float2*)&ss[lr + 8][lc] = make_float2(w10, w11);
            }
        }
        __syncthreads();

        // ---- stage 2: acc2 += ss @ v  (warp m32 x d16)
        const uint32 vb = vt_u + (uint32)buf*32*68*4 + ((wn*16 + b_ro)*68 + b_co)*4;
        #pragma unroll
        for (int kk = 0; kk < 64; kk += 8) {
            uint32 A0[4], A1[4];
            ldsm_x4(A0[0], A0[1], A0[2], A0[3], sa0 + kk*4);
            ldsm_x4(A1[0], A1[1], A1[2], A1[3], sa1 + kk*4);
            #pragma unroll
            for (int j = 0; j < 2; j++) {
                uint32 b0, b1;
                ldsm_x2(b0, b1, vb + (j*8*68 + kk)*4);
                mma_tf32(acc2[0][j], A0[0], A0[1], A0[2], A0[3], b0, b1);
                mma_tf32(acc2[1][j], A1[0], A1[1], A1[2], A1[3], b0, b1);
            }
        }
        __syncthreads();
    }

    #pragma unroll
    for (int mi = 0; mi < 2; mi++) {
        const int row0 = n0 + wm*32 + mi*16 + g;
        #pragma unroll
        for (int j = 0; j < 2; j++) {
            const int col = h*32 + wn*16 + j*8 + 2*tg;
            *(float2*)&g_sattn[(b*SEQ + row0    )*128 + col] = make_float2(acc2[mi][j].x, acc2[mi][j].y);
            *(float2*)&g_sattn[(b*SEQ + row0 + 8)*128 + col] = make_float2(acc2[mi][j].z, acc2[mi][j].w);
        }
    }
}

// ---------------- kernel 3: relative-position attention ----------------
// grid (32, 2, 4): n-tile 64, d-tile 64, batch. 8 warps = 2n x 4d (warp n32 x d16).
// Toeplitz A fragments: SCALAR loads from the staged pos_w slab (ldmatrix is
// 4-byte shifted per row -> misaligned; scalar LDS is legal and mostly broadcast).
// V B-fragments via ldmatrix; vt tiles double-buffered with cp.async.
// dyn smem: swl 4096 | vts 2x64x68 = 51200 B
#define POS_SMEM 51200
__global__ __launch_bounds__(256, 2) void pos_kernel(const float* __restrict__ pos_w)
{
    extern __shared__ float sm[];
    float* swl = sm;                                   // 4096 (tf32-rounded pos_w)
    float (*vts)[68] = (float(*)[68])(sm + 4096);      // 2*64 rows

    const int n0 = blockIdx.x * 64;
    const int d0 = blockIdx.y * 64;
    const int b  = blockIdx.z;
    const int t = threadIdx.x, w = t >> 5, lane = t & 31;
    const int wmn = w & 1, wd = w >> 1;     // 2 n-groups (n32), 4 d-groups (d16)
    const int g = lane >> 2, tg = lane & 3;

    const int l16  = lane & 15;
    const int b_ro = l16 & 7;
    const int b_co = (l16 >> 3) << 2;

    const uint32 vt_u = smem_u32(&vts[0][0]);
    const float* vtp = g_vt + (b*128 + d0)*SEQ;

    for (int i = t; i < 4095; i += 256) swl[i] = tf32f(pos_w[i]);
    if (t == 0) swl[4095] = 0.f;

    // first vt tile: 64 rows x 64 floats
    #pragma unroll
    for (int c = t; c < 1024; c += 256) {
        int r = c >> 4, s = (c & 15) << 2;
        cp16(vt_u + (r*68 + s)*4, vtp + r*SEQ + s);
    }
    CP_COMMIT();

    float4 acc[2][2];
    #pragma unroll
    for (int mi = 0; mi < 2; mi++)
        #pragma unroll
        for (int j = 0; j < 2; j++) acc[mi][j] = make_float4(0.f, 0.f, 0.f, 0.f);

    // A element (row r, col c) = swl[2047 + m0 + c - n0 - r]
    // per-lane base (row = wmn*32 + g, col = tg):
    const int abase = 2047 - n0 - wmn*32 - g + tg;

    for (int it = 0; it < 32; ++it) {
        const int m0 = it * 64;
        const int buf = it & 1;
        if (it < 31) {
            const int m1 = m0 + 64, nb = buf ^ 1;
            #pragma unroll
            for (int c = t; c < 1024; c += 256) {
                int r = c >> 4, s = (c & 15) << 2;
                cp16(vt_u + ((nb*64 + r)*68 + s)*4, vtp + r*SEQ + m1 + s);
            }
            CP_COMMIT();
            CP_WAIT1();
        } else {
            CP_WAIT0();
        }
        __syncthreads();

        const uint32 vb = vt_u + (uint32)buf*64*68*4 + ((wd*16 + b_ro)*68 + b_co)*4;
        const float* ab = swl + abase + m0;
        #pragma unroll
        for (int kk = 0; kk < 64; kk += 8) {
            // A fragments, scalar loads (Toeplitz shifts of 1 float/row)
            uint32 A0[4], A1[4];
            {
                const float* p = ab + kk;          // rows wmn*32 + {g, g+8}
                A0[0] = fb(p[0]);   A0[1] = fb(p[-8]);
                A0[2] = fb(p[4]);   A0[3] = fb(p[-4]);
                const float* q = p - 16;           // rows +16
                A1[0] = fb(q[0]);   A1[1] = fb(q[-8]);
                A1[2] = fb(q[4]);   A1[3] = fb(q[-4]);
            }
            #pragma unroll
            for (int j = 0; j < 2; j++) {
                uint32 b0, b1;
                ldsm_x2(b0, b1, vb + (j*8*68 + kk)*4);
                mma_tf32(acc[0][j], A0[0], A0[1], A0[2], A0[3], b0, b1);
                mma_tf32(acc[1][j], A1[0], A1[1], A1[2], A1[3], b0, b1);
            }
        }
        __syncthreads();
    }

    #pragma unroll
    for (int mi = 0; mi < 2; mi++) {
        const int row0 = n0 + wmn*32 + mi*16 + g;
        #pragma unroll
        for (int j = 0; j < 2; j++) {
            const int col = d0 + wd*16 + j*8 + 2*tg;
            *(float2*)&g_pattn[(b*SEQ + row0    )*128 + col] = make_float2(acc[mi][j].x, acc[mi][j].y);
            *(float2*)&g_pattn[(b*SEQ + row0 + 8)*128 + col] = make_float2(acc[mi][j].z, acc[mi][j].w);
        }
    }
}

// ---------------- kernel 4: LayerNorm(concat)*gamma+beta, times u ----------------
__global__ __launch_bounds__(256) void ln_kernel(const float* __restrict__ gamma,
                                                 const float* __restrict__ beta)
{
    const int w = threadIdx.x >> 5, l = threadIdx.x & 31;
    const int row = blockIdx.x * 8 + w;

    float4 sa = *(const float4*)&g_sattn[row * 128 + l*4];
    float4 pa = *(const float4*)&g_pattn[row * 128 + l*4];

    float sum = sa.x + sa.y + sa.z + sa.w + pa.x + pa.y + pa.z + pa.w;
    #pragma unroll
    for (int o = 16; o > 0; o >>= 1) sum += __shfl_xor_sync(0xffffffffu, sum, o);
    float mean = sum * (1.f / 256.f);

    float dx0 = sa.x - mean, dx1 = sa.y - mean, dx2 = sa.z - mean, dx3 = sa.w - mean;
    float dy0 = pa.x - mean, dy1 = pa.y - mean, dy2 = pa.z - mean, dy3 = pa.w - mean;
    float s2 = dx0*dx0 + dx1*dx1 + dx2*dx2 + dx3*dx3
             + dy0*dy0 + dy1*dy1 + dy2*dy2 + dy3*dy3;
    #pragma unroll
    for (int o = 16; o > 0; o >>= 1) s2 += __shfl_xor_sync(0xffffffffu, s2, o);
    float r = rsqrtf(s2 * (1.f / 256.f) + 1e-3f);

    float4 ga0 = *(const float4*)&gamma[l*4];
    float4 be0 = *(const float4*)&beta[l*4];
    float4 ga1 = *(const float4*)&gamma[128 + l*4];
    float4 be1 = *(const float4*)&beta[128 + l*4];
    float4 u0  = *(const float4*)&g_u[row * 256 + l*4];
    float4 u1  = *(const float4*)&g_u[row * 256 + 128 + l*4];

    float4 o0, o1;
    o0.x = u0.x * (dx0 * r * ga0.x + be0.x);
    o0.y = u0.y * (dx1 * r * ga0.y + be0.y);
    o0.z = u0.z * (dx2 * r * ga0.z + be0.z);
    o0.w = u0.w * (dx3 * r * ga0.w + be0.w);
    o1.x = u1.x * (dy0 * r * ga1.x + be1.x);
    o1.y = u1.y * (dy1 * r * ga1.y + be1.y);
    o1.z = u1.z * (dy2 * r * ga1.z + be1.z);
    o1.w = u1.w * (dy3 * r * ga1.w + be1.w);

    *(float4*)&g_g[row * 256 + l*4]       = o0;
    *(float4*)&g_g[row * 256 + 128 + l*4] = o1;
}

// ---------------- kernel 5: final GEMM + relu + residual (f32x2 SIMT, full precision) ----------------
__device__ __forceinline__ ull pack2(float lo, float hi) {
    ull r;
    asm("mov.b64 %0, {%1, %2};" : "=l"(r) : "r"(__float_as_uint(lo)), "r"(__float_as_uint(hi)));
    return r;
}
__device__ __forceinline__ ull fma2(ull a, ull b, ull c) {
    ull d;
    asm("fma.rn.f32x2 %0, %1, %2, %3;" : "=l"(d) : "l"(a), "l"(b), "l"(c));
    return d;
}
__device__ __forceinline__ float2 unpack2(ull v) {
    unsigned lo, hi;
    asm("mov.b64 {%0, %1}, %2;" : "=r"(lo), "=r"(hi) : "l"(v));
    return make_float2(__uint_as_float(lo), __uint_as_float(hi));
}

__global__ __launch_bounds__(256) void final_kernel(const float* __restrict__ x,
                                                    const float* __restrict__ Wf,
                                                    const float* __restrict__ bf,
                                                    float* __restrict__ out)
{
    __shared__ float gs[32][36];
    __shared__ float ws[32][128];

    const int r0 = blockIdx.x * 32;
    const int t  = threadIdx.x, ty = t >> 5, tx = t & 31;

    ull acc[4][2];
    #pragma unroll
    for (int i = 0; i < 4; i++) { acc[i][0] = 0ull; acc[i][1] = 0ull; }

    for (int kc = 0; kc < 256; kc += 32) {
        #pragma unroll
        for (int i = t; i < 32*32; i += 256) {
            int rr = i >> 5, cc = i & 31;
            gs[rr][cc] = g_g[(r0 + rr) * 256 + kc + cc];
        }
        #pragma unroll
        for (int i = t; i < 32*128; i += 256) {
            int rr = i >> 7, cc = i & 127;
            ws[rr][cc] = Wf[(kc + rr) * 128 + cc];
        }
        __syncthreads();

        #pragma unroll
        for (int kk = 0; kk < 32; kk += 4) {
            float4 a[4];
            #pragma unroll
            for (int i = 0; i < 4; i++)
                a[i] = *(const float4*)&gs[ty*4 + i][kk];
            #pragma unroll
            for (int q = 0; q < 4; q++) {
                ulonglong2 bp = *(const ulonglong2*)&ws[kk + q][tx*4];
                #pragma unroll
                for (int i = 0; i < 4; i++) {
                    float av = (q == 0) ? a[i].x : (q == 1) ? a[i].y : (q == 2) ? a[i].z : a[i].w;
                    ull ap = pack2(av, av);
                    acc[i][0] = fma2(ap, bp.x, acc[i][0]);
                    acc[i][1] = fma2(ap, bp.y, acc[i][1]);
                }
            }
        }
        __syncthreads();
    }

    #pragma unroll
    for (int i = 0; i < 4; i++) {
        int row = r0 + ty*4 + i;
        float2 p0 = unpack2(acc[i][0]);
        float2 p1 = unpack2(acc[i][1]);
        float o[4] = {p0.x, p0.y, p1.x, p1.y};
        float4 xr = *(const float4*)&x[row * 128 + tx*4];
        float xv[4] = {xr.x, xr.y, xr.z, xr.w};
        float4 res;
        float* rp = (float*)&res;
        #pragma unroll
        for (int j = 0; j < 4; j++) {
            int c = tx*4 + j;
            rp[j] = fmaxf(o[j] + bf[c], 0.f) + xv[j];
        }
        *(float4*)&out[row * 128 + tx*4] = res;
    }
}

// ---------------- launcher ----------------
extern "C" void kernel_launch(void* const* d_in, const int* in_sizes, int n_in,
                              void* d_out, int out_size)
{
    const float* x      = (const float*)d_in[0];
    const float* Wq     = (const float*)d_in[1];
    const float* bq     = (const float*)d_in[2];
    const float* Wk     = (const float*)d_in[3];
    const float* bk     = (const float*)d_in[4];
    const float* Wv     = (const float*)d_in[5];
    const float* bv     = (const float*)d_in[6];
    const float* Wu     = (const float*)d_in[7];
    const float* bu     = (const float*)d_in[8];
    const float* pos_w  = (const float*)d_in[9];
    const float* gamma  = (const float*)d_in[10];
    const float* beta   = (const float*)d_in[11];
    const float* Wf     = (const float*)d_in[12];
    const float* bf     = (const float*)d_in[13];
    float* out = (float*)d_out;

    cudaFuncSetAttribute(attn_kernel, cudaFuncAttributeMaxDynamicSharedMemorySize, ATTN_SMEM);
    cudaFuncSetAttribute(pos_kernel,  cudaFuncAttributeMaxDynamicSharedMemorySize, POS_SMEM);

    proj_kernel<<<dim3(5, ROWS/64), 256>>>(x, Wq, bq, Wk, bk, Wv, bv, Wu, bu);
    attn_kernel<<<dim3(SEQ/128, BATCH*4), 256, ATTN_SMEM>>>();
    pos_kernel<<<dim3(SEQ/64, 2, BATCH), 256, POS_SMEM>>>(pos_w);
    ln_kernel<<<ROWS/8, 256>>>(gamma, beta);
    final_kernel<<<ROWS/32, 256>>>(x, Wf, bf, out);
}

// round 6
// speedup vs baseline: 1.4791x; 1.4791x over previous
#include <cuda_runtime.h>
#include <math.h>

#define BATCH 4
#define SEQ   2048
#define DIM   128
#define ROWS  (BATCH*SEQ)   // 8192

typedef unsigned long long ull;
typedef unsigned int uint32;

// ---------------- scratch (no allocation allowed) ----------------
__device__ float g_q[ROWS*DIM];       // tf32-rounded, PRE-SCALED by 1/sqrt(32)
__device__ float g_k[ROWS*DIM];       // tf32-rounded
__device__ float g_vt[ROWS*DIM];      // tf32-rounded, TRANSPOSED: [b][d=128][token=2048]
__device__ float g_u[ROWS*2*DIM];     // full f32
__device__ float g_sattn[ROWS*DIM];
__device__ float g_pattn[ROWS*DIM];
__device__ float g_g[ROWS*2*DIM];

__device__ __forceinline__ float silu_f(float v) {
    return v * (1.f / (1.f + __expf(-v)));
}
__device__ __forceinline__ float tanh_ap(float x) {
    float y; asm("tanh.approx.f32 %0, %1;" : "=f"(y) : "f"(x)); return y;
}
// silu via 1 MUFU: x*sigmoid(x) = x*(0.5*tanh(0.5x)+0.5)
__device__ __forceinline__ float silu_t(float x) {
    return fmaf(x, 0.5f * tanh_ap(0.5f * x), 0.5f * x);
}
__device__ __forceinline__ uint32 tf32_of(float f) {
    uint32 u; asm("cvt.rna.tf32.f32 %0, %1;" : "=r"(u) : "f"(f)); return u;
}
__device__ __forceinline__ float tf32f(float f) { return __uint_as_float(tf32_of(f)); }
__device__ __forceinline__ uint32 fb(float f) { return __float_as_uint(f); }
__device__ __forceinline__ uint32 smem_u32(const void* p) {
    return (uint32)__cvta_generic_to_shared(p);
}

__device__ __forceinline__ void mma_tf32(float4& d, uint32 a0, uint32 a1, uint32 a2, uint32 a3,
                                         uint32 b0, uint32 b1) {
    asm volatile(
        "mma.sync.aligned.m16n8k8.row.col.f32.tf32.tf32.f32 "
        "{%0,%1,%2,%3}, {%4,%5,%6,%7}, {%8,%9}, {%0,%1,%2,%3};"
        : "+f"(d.x), "+f"(d.y), "+f"(d.z), "+f"(d.w)
        : "r"(a0), "r"(a1), "r"(a2), "r"(a3), "r"(b0), "r"(b1));
}
__device__ __forceinline__ void ldsm_x4(uint32& r0, uint32& r1, uint32& r2, uint32& r3, uint32 addr) {
    asm volatile("ldmatrix.sync.aligned.m8n8.x4.shared.b16 {%0,%1,%2,%3}, [%4];"
        : "=r"(r0), "=r"(r1), "=r"(r2), "=r"(r3) : "r"(addr));
}
__device__ __forceinline__ void ldsm_x2(uint32& r0, uint32& r1, uint32 addr) {
    asm volatile("ldmatrix.sync.aligned.m8n8.x2.shared.b16 {%0,%1}, [%2];"
        : "=r"(r0), "=r"(r1) : "r"(addr));
}
__device__ __forceinline__ void cp16(uint32 dst, const float* src) {
    asm volatile("cp.async.ca.shared.global [%0], [%1], 16;" :: "r"(dst), "l"(src));
}
#define CP_COMMIT() asm volatile("cp.async.commit_group;")
#define CP_WAIT1()  asm volatile("cp.async.wait_group 1;")
#define CP_WAIT0()  asm volatile("cp.async.wait_group 0;")

// ---------------- kernel 1: fused q/k/v/u projections (tf32 mma) ----------------
// grid (5, 128). seg 0=q (pre-scaled 1/sqrt(32)), 1=k, 2=v(transposed out), 3/4=u halves.
__global__ __launch_bounds__(256) void proj_kernel(
    const float* __restrict__ x,
    const float* __restrict__ Wq, const float* __restrict__ bq,
    const float* __restrict__ Wk, const float* __restrict__ bk,
    const float* __restrict__ Wv, const float* __restrict__ bv,
    const float* __restrict__ Wu, const float* __restrict__ bu)
{
    __shared__ float xs[64][36];
    __shared__ float ws[32][136];

    const int seg = blockIdx.x;
    const int r0  = blockIdx.y * 64;

    const float* W; const float* bias; int ldw, c0;
    if (seg == 0)      { W = Wq; bias = bq; ldw = 128; c0 = 0; }
    else if (seg == 1) { W = Wk; bias = bk; ldw = 128; c0 = 0; }
    else if (seg == 2) { W = Wv; bias = bv; ldw = 128; c0 = 0; }
    else               { W = Wu; bias = bu; ldw = 256; c0 = (seg - 3) * 128; }

    const int t = threadIdx.x;
    const int w = t >> 5, lane = t & 31;
    const int wm = w & 3, wn = w >> 2;
    const int g = lane >> 2, tg = lane & 3;

    float4 acc[8];
    #pragma unroll
    for (int j = 0; j < 8; j++) acc[j] = make_float4(0.f, 0.f, 0.f, 0.f);

    for (int kc = 0; kc < 128; kc += 32) {
        #pragma unroll
        for (int i = t*4; i < 64*32; i += 256*4) {
            int rr = i >> 5, cc = i & 31;
            float4 v4 = *(const float4*)&x[(r0 + rr) * 128 + kc + cc];
            xs[rr][cc+0] = tf32f(v4.x); xs[rr][cc+1] = tf32f(v4.y);
            xs[rr][cc+2] = tf32f(v4.z); xs[rr][cc+3] = tf32f(v4.w);
        }
        #pragma unroll
        for (int i = t*4; i < 32*128; i += 256*4) {
            int rr = i >> 7, cc = i & 127;
            float4 v4 = *(const float4*)&W[(kc + rr) * ldw + c0 + cc];
            ws[rr][cc+0] = tf32f(v4.x); ws[rr][cc+1] = tf32f(v4.y);
            ws[rr][cc+2] = tf32f(v4.z); ws[rr][cc+3] = tf32f(v4.w);
        }
        __syncthreads();

        #pragma unroll
        for (int kk = 0; kk < 32; kk += 8) {
            uint32 a0 = fb(xs[wm*16 + g    ][kk + tg    ]);
            uint32 a1 = fb(xs[wm*16 + g + 8][kk + tg    ]);
            uint32 a2 = fb(xs[wm*16 + g    ][kk + tg + 4]);
            uint32 a3 = fb(xs[wm*16 + g + 8][kk + tg + 4]);
            #pragma unroll
            for (int j = 0; j < 8; j++) {
                uint32 b0 = fb(ws[kk + tg    ][wn*64 + j*8 + g]);
                uint32 b1 = fb(ws[kk + tg + 4][wn*64 + j*8 + g]);
                mma_tf32(acc[j], a0, a1, a2, a3, b0, b1);
            }
        }
        __syncthreads();
    }

    if (seg == 2) {
        // v: transposed tf32 store into g_vt[b][d][token]
        const int bb = r0 >> 11;
        const int tok = (r0 & 2047) + wm*16 + g;
        #pragma unroll
        for (int j = 0; j < 8; j++) {
            int col = wn*64 + j*8 + 2*tg;
            float b0v = bias[col], b1v = bias[col + 1];
            float v00 = tf32f(silu_f(acc[j].x + b0v));
            float v01 = tf32f(silu_f(acc[j].y + b1v));
            float v10 = tf32f(silu_f(acc[j].z + b0v));
            float v11 = tf32f(silu_f(acc[j].w + b1v));
            float* p0 = &g_vt[(bb*128 + col) * SEQ + tok];
            p0[0] = v00; p0[8] = v10;
            float* p1 = p0 + SEQ;
            p1[0] = v01; p1[8] = v11;
        }
    } else {
        float* out = (seg == 0) ? g_q : (seg == 1) ? g_k : g_u;
        bool act = (seg <= 1);
        const float mult = (seg == 0) ? 0.17677669529663687f : 1.0f;  // 1/sqrt(32) into q
        #pragma unroll
        for (int j = 0; j < 8; j++) {
            int col = c0 + wn*64 + j*8 + 2*tg;
            float b0v = bias[col], b1v = bias[col + 1];
            int row0 = r0 + wm*16 + g;
            float v00 = acc[j].x + b0v, v01 = acc[j].y + b1v;
            float v10 = acc[j].z + b0v, v11 = acc[j].w + b1v;
            if (act) {
                v00 = tf32f(silu_f(v00) * mult); v01 = tf32f(silu_f(v01) * mult);
                v10 = tf32f(silu_f(v10) * mult); v11 = tf32f(silu_f(v11) * mult);
            }
            *(float2*)&out[row0 * ldw + col]       = make_float2(v00, v01);
            *(float2*)&out[(row0 + 8) * ldw + col] = make_float2(v10, v11);
        }
    }
}

// ---------------- kernel 2: causal attention, diagonal-paired tiles ----------------
// grid (8, 16): block p handles m-tiles {15-p, p} (128 rows each) -> uniform 34 key-iters.
// 512 threads = 16 warps (4m x 4n). dyn smem:
//   qs 128x36 | ks 2x64x36 | vts 2x32x68 | ss 128x68 = 22272 floats = 89088 B
#define ATTN_SMEM 89088
__global__ __launch_bounds__(512, 1) void attn_kernel()
{
    extern __shared__ float sm[];
    float (*qs)[36]  = (float(*)[36])sm;                 // 128 rows
    float (*ks)[36]  = (float(*)[36])(sm + 4608);        // 2*64 rows
    float (*vts)[68] = (float(*)[68])(sm + 9216);        // 2*32 rows
    float (*ss)[68]  = (float(*)[68])(sm + 13568);       // 128 rows

    const int p = blockIdx.x;                  // 0..7
    const int b = blockIdx.y >> 2, h = blockIdx.y & 3;
    const int t = threadIdx.x, w = t >> 5, lane = t & 31;
    const int wm = w & 3, wn = w >> 2;         // 4m x 4n
    const int g = lane >> 2, tg = lane & 3;

    const float* kp  = g_k  + (b*SEQ)*128 + h*32;
    const float* vtp = g_vt + (b*128 + h*32)*SEQ;

    const uint32 qs_u = smem_u32(&qs[0][0]);
    const uint32 ks_u = smem_u32(&ks[0][0]);
    const uint32 vt_u = smem_u32(&vts[0][0]);
    const uint32 ss_u = smem_u32(&ss[0][0]);

    // ldmatrix lane-address components
    const int lrow = lane & 7;
    const int sel4 = lane >> 3;
    const int a_ro = ((sel4 & 1) << 3) + lrow;     // row-in-16 for x4
    const int a_co = (sel4 & 2) ? 4 : 0;           // k-offset for x4
    const int l16  = lane & 15;
    const int b_ro = l16 & 7;
    const int b_co = (l16 >> 3) << 2;

    const uint32 qa0 = qs_u + ((wm*32 + a_ro)*36 + a_co)*4;
    const uint32 qa1 = qa0 + 16*36*4;
    const uint32 sa0 = ss_u + ((wm*32 + a_ro)*68 + a_co)*4;
    const uint32 sa1 = sa0 + 16*68*4;

    #pragma unroll
    for (int ph = 0; ph < 2; ph++) {
        const int tile = ph ? p : 15 - p;        // long phase first
        const int n0 = tile * 128;
        const float* qp = g_q + (b*SEQ + n0)*128 + h*32;

        // q tile: 128 rows x 32 floats (1024 float4)
        #pragma unroll
        for (int c = t; c < 1024; c += 512) {
            int r = c >> 3, s = (c & 7) << 2;
            cp16(qs_u + (r*36 + s)*4, qp + r*128 + s);
        }
        // first k/vt tile
        {
            int c = t;
            if (c < 512) {
                int r = c >> 3, s = (c & 7) << 2;
                cp16(ks_u + (r*36 + s)*4, kp + r*128 + s);
            }
            int r = c >> 4, s = (c & 15) << 2;
            cp16(vt_u + (r*68 + s)*4, vtp + r*SEQ + s);
        }
        CP_COMMIT();

        float4 acc2[2];
        acc2[0] = make_float4(0.f, 0.f, 0.f, 0.f);
        acc2[1] = make_float4(0.f, 0.f, 0.f, 0.f);

        const int iters = 2*tile + 2;
        for (int it = 0; it < iters; ++it) {
            const int m0 = it * 64;
            const int buf = it & 1;
            if (it + 1 < iters) {
                const int m1 = m0 + 64, nb = buf ^ 1;
                int c = t;
                if (c < 512) {
                    int r = c >> 3, s = (c & 7) << 2;
                    cp16(ks_u + ((nb*64 + r)*36 + s)*4, kp + (m1 + r)*128 + s);
                }
                int r = c >> 4, s = (c & 15) << 2;
                cp16(vt_u + ((nb*32 + r)*68 + s)*4, vtp + r*SEQ + m1 + s);
                CP_COMMIT();
                CP_WAIT1();
            } else {
                CP_WAIT0();
            }
            __syncthreads();

            // ---- stage 1: scores m128 x n64 (warp m32 x n16)
            float4 sc[2][2];
            #pragma unroll
            for (int mi = 0; mi < 2; mi++)
                #pragma unroll
                for (int j = 0; j < 2; j++) sc[mi][j] = make_float4(0.f, 0.f, 0.f, 0.f);

            const uint32 kb = ks_u + (uint32)buf*64*36*4 + ((wn*16 + b_ro)*36 + b_co)*4;
            #pragma unroll
            for (int kk = 0; kk < 32; kk += 8) {
                uint32 A0[4], A1[4];
                ldsm_x4(A0[0], A0[1], A0[2], A0[3], qa0 + kk*4);
                ldsm_x4(A1[0], A1[1], A1[2], A1[3], qa1 + kk*4);
                #pragma unroll
                for (int j = 0; j < 2; j++) {
                    uint32 b0, b1;
                    ldsm_x2(b0, b1, kb + (j*8*36 + kk)*4);
                    mma_tf32(sc[0][j], A0[0], A0[1], A0[2], A0[3], b0, b1);
                    mma_tf32(sc[1][j], A1[0], A1[1], A1[2], A1[3], b0, b1);
                }
            }

            // mask + square + silu(tanh) -> ss (tf32)
            #pragma unroll
            for (int mi = 0; mi < 2; mi++) {
                const int lr = wm*32 + mi*16 + g;
                const int nrow0 = n0 + lr, nrow1 = nrow0 + 8;
                #pragma unroll
                for (int j = 0; j < 2; j++) {
                    const int lc = wn*16 + j*8 + 2*tg;
                    const int cc = m0 + lc;
                    float s;
                    s = sc[mi][j].x; s = (cc     <= nrow0) ? s*s : 0.f; float w00 = tf32f(silu_t(s));
                    s = sc[mi][j].y; s = (cc + 1 <= nrow0) ? s*s : 0.f; float w01 = tf32f(silu_t(s));
                    s = sc[mi][j].z; s = (cc     <= nrow1) ? s*s : 0.f; float w10 = tf32f(silu_t(s));
                    s = sc[mi][j].w; s = (cc + 1 <= nrow1) ? s*s : 0.f; float w11 = tf32f(silu_t(s));
                    *(float2*)&ss[lr    ][lc] = make_float2(w00, w01);
                    *(float2*)&ss[lr + 8][lc] = make_float2(w10, w11);
                }
            }
            __syncthreads();

            // ---- stage 2: acc2 += ss @ v  (warp m32 x d8)
            const uint32 vb = vt_u + (uint32)buf*32*68*4 + ((wn*8 + b_ro)*68 + b_co)*4;
            #pragma unroll
            for (int kk = 0; kk < 64; kk += 8) {
                uint32 A0[4], A1[4];
                ldsm_x4(A0[0], A0[1], A0[2], A0[3], sa0 + kk*4);
                ldsm_x4(A1[0], A1[1], A1[2], A1[3], sa1 + kk*4);
                uint32 b0, b1;
                ldsm_x2(b0, b1, vb + kk*4);
                mma_tf32(acc2[0], A0[0], A0[1], A0[2], A0[3], b0, b1);
                mma_tf32(acc2[1], A1[0], A1[1], A1[2], A1[3], b0, b1);
            }
            __syncthreads();
        }

        #pragma unroll
        for (int mi = 0; mi < 2; mi++) {
            const int row0 = n0 + wm*32 + mi*16 + g;
            const int col  = h*32 + wn*8 + 2*tg;
            *(float2*)&g_sattn[(b*SEQ + row0    )*128 + col] = make_float2(acc2[mi].x, acc2[mi].y);
            *(float2*)&g_sattn[(b*SEQ + row0 + 8)*128 + col] = make_float2(acc2[mi].z, acc2[mi].w);
        }
    }
}

// ---------------- kernel 3: relative-position attention ----------------
// grid (32, 2, 4): n-tile 64, d-tile 64, batch. 8 warps = 2n x 4d (warp n32 x d16).
// Toeplitz A fragments via scalar LDS; V B-fragments via ldmatrix; cp.async pipeline.
// dyn smem: swl 4096 | vts 2x64x68 = 51200 B
#define POS_SMEM 51200
__global__ __launch_bounds__(256, 2) void pos_kernel(const float* __restrict__ pos_w)
{
    extern __shared__ float sm[];
    float* swl = sm;                                   // 4096 (tf32-rounded pos_w)
    float (*vts)[68] = (float(*)[68])(sm + 4096);      // 2*64 rows

    const int n0 = blockIdx.x * 64;
    const int d0 = blockIdx.y * 64;
    const int b  = blockIdx.z;
    const int t = threadIdx.x, w = t >> 5, lane = t & 31;
    const int wmn = w & 1, wd = w >> 1;     // 2 n-groups (n32), 4 d-groups (d16)
    const int g = lane >> 2, tg = lane & 3;

    const int l16  = lane & 15;
    const int b_ro = l16 & 7;
    const int b_co = (l16 >> 3) << 2;

    const uint32 vt_u = smem_u32(&vts[0][0]);
    const float* vtp = g_vt + (b*128 + d0)*SEQ;

    for (int i = t; i < 4095; i += 256) swl[i] = tf32f(pos_w[i]);
    if (t == 0) swl[4095] = 0.f;

    // first vt tile: 64 rows x 64 floats
    #pragma unroll
    for (int c = t; c < 1024; c += 256) {
        int r = c >> 4, s = (c & 15) << 2;
        cp16(vt_u + (r*68 + s)*4, vtp + r*SEQ + s);
    }
    CP_COMMIT();

    float4 acc[2][2];
    #pragma unroll
    for (int mi = 0; mi < 2; mi++)
        #pragma unroll
        for (int j = 0; j < 2; j++) acc[mi][j] = make_float4(0.f, 0.f, 0.f, 0.f);

    // A element (row r, col c) = swl[2047 + m0 + c - n0 - r]
    const int abase = 2047 - n0 - wmn*32 - g + tg;

    for (int it = 0; it < 32; ++it) {
        const int m0 = it * 64;
        const int buf = it & 1;
        if (it < 31) {
            const int m1 = m0 + 64, nb = buf ^ 1;
            #pragma unroll
            for (int c = t; c < 1024; c += 256) {
                int r = c >> 4, s = (c & 15) << 2;
                cp16(vt_u + ((nb*64 + r)*68 + s)*4, vtp + r*SEQ + m1 + s);
            }
            CP_COMMIT();
            CP_WAIT1();
        } else {
            CP_WAIT0();
        }
        __syncthreads();

        const uint32 vb = vt_u + (uint32)buf*64*68*4 + ((wd*16 + b_ro)*68 + b_co)*4;
        const float* ab = swl + abase + m0;
        #pragma unroll
        for (int kk = 0; kk < 64; kk += 8) {
            uint32 A0[4], A1[4];
            {
                const float* pp = ab + kk;         // rows wmn*32 + {g, g+8}
                A0[0] = fb(pp[0]);   A0[1] = fb(pp[-8]);
                A0[2] = fb(pp[4]);   A0[3] = fb(pp[-4]);
                const float* qq = pp - 16;         // rows +16
                A1[0] = fb(qq[0]);   A1[1] = fb(qq[-8]);
                A1[2] = fb(qq[4]);   A1[3] = fb(qq[-4]);
            }
            #pragma unroll
            for (int j = 0; j < 2; j++) {
                uint32 b0, b1;
                ldsm_x2(b0, b1, vb + (j*8*68 + kk)*4);
                mma_tf32(acc[0][j], A0[0], A0[1], A0[2], A0[3], b0, b1);
                mma_tf32(acc[1][j], A1[0], A1[1], A1[2], A1[3], b0, b1);
            }
        }
        __syncthreads();
    }

    #pragma unroll
    for (int mi = 0; mi < 2; mi++) {
        const int row0 = n0 + wmn*32 + mi*16 + g;
        #pragma unroll
        for (int j = 0; j < 2; j++) {
            const int col = d0 + wd*16 + j*8 + 2*tg;
            *(float2*)&g_pattn[(b*SEQ + row0    )*128 + col] = make_float2(acc[mi][j].x, acc[mi][j].y);
            *(float2*)&g_pattn[(b*SEQ + row0 + 8)*128 + col] = make_float2(acc[mi][j].z, acc[mi][j].w);
        }
    }
}

// ---------------- kernel 4: LayerNorm(concat)*gamma+beta, times u ----------------
__global__ __launch_bounds__(256) void ln_kernel(const float* __restrict__ gamma,
                                                 const float* __restrict__ beta)
{
    const int w = threadIdx.x >> 5, l = threadIdx.x & 31;
    const int row = blockIdx.x * 8 + w;

    float4 sa = *(const float4*)&g_sattn[row * 128 + l*4];
    float4 pa = *(const float4*)&g_pattn[row * 128 + l*4];

    float sum = sa.x + sa.y + sa.z + sa.w + pa.x + pa.y + pa.z + pa.w;
    #pragma unroll
    for (int o = 16; o > 0; o >>= 1) sum += __shfl_xor_sync(0xffffffffu, sum, o);
    float mean = sum * (1.f / 256.f);

    float dx0 = sa.x - mean, dx1 = sa.y - mean, dx2 = sa.z - mean, dx3 = sa.w - mean;
    float dy0 = pa.x - mean, dy1 = pa.y - mean, dy2 = pa.z - mean, dy3 = pa.w - mean;
    float s2 = dx0*dx0 + dx1*dx1 + dx2*dx2 + dx3*dx3
             + dy0*dy0 + dy1*dy1 + dy2*dy2 + dy3*dy3;
    #pragma unroll
    for (int o = 16; o > 0; o >>= 1) s2 += __shfl_xor_sync(0xffffffffu, s2, o);
    float r = rsqrtf(s2 * (1.f / 256.f) + 1e-3f);

    float4 ga0 = *(const float4*)&gamma[l*4];
    float4 be0 = *(const float4*)&beta[l*4];
    float4 ga1 = *(const float4*)&gamma[128 + l*4];
    float4 be1 = *(const float4*)&beta[128 + l*4];
    float4 u0  = *(const float4*)&g_u[row * 256 + l*4];
    float4 u1  = *(const float4*)&g_u[row * 256 + 128 + l*4];

    float4 o0, o1;
    o0.x = u0.x * (dx0 * r * ga0.x + be0.x);
    o0.y = u0.y * (dx1 * r * ga0.y + be0.y);
    o0.z = u0.z * (dx2 * r * ga0.z + be0.z);
    o0.w = u0.w * (dx3 * r * ga0.w + be0.w);
    o1.x = u1.x * (dy0 * r * ga1.x + be1.x);
    o1.y = u1.y * (dy1 * r * ga1.y + be1.y);
    o1.z = u1.z * (dy2 * r * ga1.z + be1.z);
    o1.w = u1.w * (dy3 * r * ga1.w + be1.w);

    *(float4*)&g_g[row * 256 + l*4]       = o0;
    *(float4*)&g_g[row * 256 + 128 + l*4] = o1;
}

// ---------------- kernel 5: final GEMM + relu + residual (f32x2 SIMT, full precision) ----------------
__device__ __forceinline__ ull pack2(float lo, float hi) {
    ull r;
    asm("mov.b64 %0, {%1, %2};" : "=l"(r) : "r"(__float_as_uint(lo)), "r"(__float_as_uint(hi)));
    return r;
}
__device__ __forceinline__ ull fma2(ull a, ull b, ull c) {
    ull d;
    asm("fma.rn.f32x2 %0, %1, %2, %3;" : "=l"(d) : "l"(a), "l"(b), "l"(c));
    return d;
}
__device__ __forceinline__ float2 unpack2(ull v) {
    unsigned lo, hi;
    asm("mov.b64 {%0, %1}, %2;" : "=r"(lo), "=r"(hi) : "l"(v));
    return make_float2(__uint_as_float(lo), __uint_as_float(hi));
}

__global__ __launch_bounds__(256) void final_kernel(const float* __restrict__ x,
                                                    const float* __restrict__ Wf,
                                                    const float* __restrict__ bf,
                                                    float* __restrict__ out)
{
    __shared__ float gs[32][36];
    __shared__ float ws[32][128];

    const int r0 = blockIdx.x * 32;
    const int t  = threadIdx.x, ty = t >> 5, tx = t & 31;

    ull acc[4][2];
    #pragma unroll
    for (int i = 0; i < 4; i++) { acc[i][0] = 0ull; acc[i][1] = 0ull; }

    for (int kc = 0; kc < 256; kc += 32) {
        #pragma unroll
        for (int i = t; i < 32*32; i += 256) {
            int rr = i >> 5, cc = i & 31;
            gs[rr][cc] = g_g[(r0 + rr) * 256 + kc + cc];
        }
        #pragma unroll
        for (int i = t; i < 32*128; i += 256) {
            int rr = i >> 7, cc = i & 127;
            ws[rr][cc] = Wf[(kc + rr) * 128 + cc];
        }
        __syncthreads();

        #pragma unroll
        for (int kk = 0; kk < 32; kk += 4) {
            float4 a[4];
            #pragma unroll
            for (int i = 0; i < 4; i++)
                a[i] = *(const float4*)&gs[ty*4 + i][kk];
            #pragma unroll
            for (int q = 0; q < 4; q++) {
                ulonglong2 bp = *(const ulonglong2*)&ws[kk + q][tx*4];
                #pragma unroll
                for (int i = 0; i < 4; i++) {
                    float av = (q == 0) ? a[i].x : (q == 1) ? a[i].y : (q == 2) ? a[i].z : a[i].w;
                    ull ap = pack2(av, av);
                    acc[i][0] = fma2(ap, bp.x, acc[i][0]);
                    acc[i][1] = fma2(ap, bp.y, acc[i][1]);
                }
            }
        }
        __syncthreads();
    }

    #pragma unroll
    for (int i = 0; i < 4; i++) {
        int row = r0 + ty*4 + i;
        float2 p0 = unpack2(acc[i][0]);
        float2 p1 = unpack2(acc[i][1]);
        float o[4] = {p0.x, p0.y, p1.x, p1.y};
        float4 xr = *(const float4*)&x[row * 128 + tx*4];
        float xv[4] = {xr.x, xr.y, xr.z, xr.w};
        float4 res;
        float* rp = (float*)&res;
        #pragma unroll
        for (int j = 0; j < 4; j++) {
            int c = tx*4 + j;
            rp[j] = fmaxf(o[j] + bf[c], 0.f) + xv[j];
        }
        *(float4*)&out[row * 128 + tx*4] = res;
    }
}

// ---------------- launcher ----------------
extern "C" void kernel_launch(void* const* d_in, const int* in_sizes, int n_in,
                              void* d_out, int out_size)
{
    const float* x      = (const float*)d_in[0];
    const float* Wq     = (const float*)d_in[1];
    const float* bq     = (const float*)d_in[2];
    const float* Wk     = (const float*)d_in[3];
    const float* bk     = (const float*)d_in[4];
    const float* Wv     = (const float*)d_in[5];
    const float* bv     = (const float*)d_in[6];
    const float* Wu     = (const float*)d_in[7];
    const float* bu     = (const float*)d_in[8];
    const float* pos_w  = (const float*)d_in[9];
    const float* gamma  = (const float*)d_in[10];
    const float* beta   = (const float*)d_in[11];
    const float* Wf     = (const float*)d_in[12];
    const float* bf     = (const float*)d_in[13];
    float* out = (float*)d_out;

    cudaFuncSetAttribute(attn_kernel, cudaFuncAttributeMaxDynamicSharedMemorySize, ATTN_SMEM);
    cudaFuncSetAttribute(pos_kernel,  cudaFuncAttributeMaxDynamicSharedMemorySize, POS_SMEM);

    proj_kernel<<<dim3(5, ROWS/64), 256>>>(x, Wq, bq, Wk, bk, Wv, bv, Wu, bu);
    attn_kernel<<<dim3(8, BATCH*4), 512, ATTN_SMEM>>>();
    pos_kernel<<<dim3(SEQ/64, 2, BATCH), 256, POS_SMEM>>>(pos_w);
    ln_kernel<<<ROWS/8, 256>>>(gamma, beta);
    final_kernel<<<ROWS/32, 256>>>(x, Wf, bf, out);
}

// round 7
// speedup vs baseline: 1.5024x; 1.0158x over previous
#include <cuda_runtime.h>
#include <math.h>

#define BATCH 4
#define SEQ   2048
#define DIM   128
#define ROWS  (BATCH*SEQ)   // 8192

typedef unsigned long long ull;
typedef unsigned int uint32;

// ---------------- scratch (no allocation allowed) ----------------
__device__ float g_q[ROWS*DIM];       // tf32-rounded, PRE-SCALED by 1/sqrt(32)
__device__ float g_k[ROWS*DIM];       // tf32-rounded
__device__ float g_vt[ROWS*DIM];      // tf32-rounded, TRANSPOSED: [b][d=128][token=2048]
__device__ float g_u[ROWS*2*DIM];     // full f32
__device__ float g_sattn[ROWS*DIM];
__device__ float g_pattn[ROWS*DIM];

__device__ __forceinline__ float silu_f(float v) {
    return v * (1.f / (1.f + __expf(-v)));
}
__device__ __forceinline__ float tanh_ap(float x) {
    float y; asm("tanh.approx.f32 %0, %1;" : "=f"(y) : "f"(x)); return y;
}
// silu via 1 MUFU: x*sigmoid(x) = x*(0.5*tanh(0.5x)+0.5)
__device__ __forceinline__ float silu_t(float x) {
    return fmaf(x, 0.5f * tanh_ap(0.5f * x), 0.5f * x);
}
__device__ __forceinline__ uint32 tf32_of(float f) {
    uint32 u; asm("cvt.rna.tf32.f32 %0, %1;" : "=r"(u) : "f"(f)); return u;
}
__device__ __forceinline__ float tf32f(float f) { return __uint_as_float(tf32_of(f)); }
__device__ __forceinline__ uint32 fb(float f) { return __float_as_uint(f); }
__device__ __forceinline__ uint32 smem_u32(const void* p) {
    return (uint32)__cvta_generic_to_shared(p);
}

__device__ __forceinline__ void mma_tf32(float4& d, uint32 a0, uint32 a1, uint32 a2, uint32 a3,
                                         uint32 b0, uint32 b1) {
    asm volatile(
        "mma.sync.aligned.m16n8k8.row.col.f32.tf32.tf32.f32 "
        "{%0,%1,%2,%3}, {%4,%5,%6,%7}, {%8,%9}, {%0,%1,%2,%3};"
        : "+f"(d.x), "+f"(d.y), "+f"(d.z), "+f"(d.w)
        : "r"(a0), "r"(a1), "r"(a2), "r"(a3), "r"(b0), "r"(b1));
}
__device__ __forceinline__ void ldsm_x4(uint32& r0, uint32& r1, uint32& r2, uint32& r3, uint32 addr) {
    asm volatile("ldmatrix.sync.aligned.m8n8.x4.shared.b16 {%0,%1,%2,%3}, [%4];"
        : "=r"(r0), "=r"(r1), "=r"(r2), "=r"(r3) : "r"(addr));
}
__device__ __forceinline__ void ldsm_x2(uint32& r0, uint32& r1, uint32 addr) {
    asm volatile("ldmatrix.sync.aligned.m8n8.x2.shared.b16 {%0,%1}, [%2];"
        : "=r"(r0), "=r"(r1) : "r"(addr));
}
__device__ __forceinline__ void cp16(uint32 dst, const float* src) {
    asm volatile("cp.async.ca.shared.global [%0], [%1], 16;" :: "r"(dst), "l"(src));
}
#define CP_COMMIT() asm volatile("cp.async.commit_group;")
#define CP_WAIT1()  asm volatile("cp.async.wait_group 1;")
#define CP_WAIT0()  asm volatile("cp.async.wait_group 0;")

// ---------------- kernel 1: fused q/k/v/u projections (tf32 mma) ----------------
// grid (5, 128). seg 0=q (pre-scaled 1/sqrt(32)), 1=k, 2=v(transposed out), 3/4=u halves.
__global__ __launch_bounds__(256) void proj_kernel(
    const float* __restrict__ x,
    const float* __restrict__ Wq, const float* __restrict__ bq,
    const float* __restrict__ Wk, const float* __restrict__ bk,
    const float* __restrict__ Wv, const float* __restrict__ bv,
    const float* __restrict__ Wu, const float* __restrict__ bu)
{
    __shared__ float xs[64][36];
    __shared__ float ws[32][136];

    const int seg = blockIdx.x;
    const int r0  = blockIdx.y * 64;

    const float* W; const float* bias; int ldw, c0;
    if (seg == 0)      { W = Wq; bias = bq; ldw = 128; c0 = 0; }
    else if (seg == 1) { W = Wk; bias = bk; ldw = 128; c0 = 0; }
    else if (seg == 2) { W = Wv; bias = bv; ldw = 128; c0 = 0; }
    else               { W = Wu; bias = bu; ldw = 256; c0 = (seg - 3) * 128; }

    const int t = threadIdx.x;
    const int w = t >> 5, lane = t & 31;
    const int wm = w & 3, wn = w >> 2;
    const int g = lane >> 2, tg = lane & 3;

    float4 acc[8];
    #pragma unroll
    for (int j = 0; j < 8; j++) acc[j] = make_float4(0.f, 0.f, 0.f, 0.f);

    for (int kc = 0; kc < 128; kc += 32) {
        #pragma unroll
        for (int i = t*4; i < 64*32; i += 256*4) {
            int rr = i >> 5, cc = i & 31;
            float4 v4 = *(const float4*)&x[(r0 + rr) * 128 + kc + cc];
            xs[rr][cc+0] = tf32f(v4.x); xs[rr][cc+1] = tf32f(v4.y);
            xs[rr][cc+2] = tf32f(v4.z); xs[rr][cc+3] = tf32f(v4.w);
        }
        #pragma unroll
        for (int i = t*4; i < 32*128; i += 256*4) {
            int rr = i >> 7, cc = i & 127;
            float4 v4 = *(const float4*)&W[(kc + rr) * ldw + c0 + cc];
            ws[rr][cc+0] = tf32f(v4.x); ws[rr][cc+1] = tf32f(v4.y);
            ws[rr][cc+2] = tf32f(v4.z); ws[rr][cc+3] = tf32f(v4.w);
        }
        __syncthreads();

        #pragma unroll
        for (int kk = 0; kk < 32; kk += 8) {
            uint32 a0 = fb(xs[wm*16 + g    ][kk + tg    ]);
            uint32 a1 = fb(xs[wm*16 + g + 8][kk + tg    ]);
            uint32 a2 = fb(xs[wm*16 + g    ][kk + tg + 4]);
            uint32 a3 = fb(xs[wm*16 + g + 8][kk + tg + 4]);
            #pragma unroll
            for (int j = 0; j < 8; j++) {
                uint32 b0 = fb(ws[kk + tg    ][wn*64 + j*8 + g]);
                uint32 b1 = fb(ws[kk + tg + 4][wn*64 + j*8 + g]);
                mma_tf32(acc[j], a0, a1, a2, a3, b0, b1);
            }
        }
        __syncthreads();
    }

    if (seg == 2) {
        // v: transposed tf32 store into g_vt[b][d][token]
        const int bb = r0 >> 11;
        const int tok = (r0 & 2047) + wm*16 + g;
        #pragma unroll
        for (int j = 0; j < 8; j++) {
            int col = wn*64 + j*8 + 2*tg;
            float b0v = bias[col], b1v = bias[col + 1];
            float v00 = tf32f(silu_f(acc[j].x + b0v));
            float v01 = tf32f(silu_f(acc[j].y + b1v));
            float v10 = tf32f(silu_f(acc[j].z + b0v));
            float v11 = tf32f(silu_f(acc[j].w + b1v));
            float* p0 = &g_vt[(bb*128 + col) * SEQ + tok];
            p0[0] = v00; p0[8] = v10;
            float* p1 = p0 + SEQ;
            p1[0] = v01; p1[8] = v11;
        }
    } else {
        float* out = (seg == 0) ? g_q : (seg == 1) ? g_k : g_u;
        bool act = (seg <= 1);
        const float mult = (seg == 0) ? 0.17677669529663687f : 1.0f;  // 1/sqrt(32) into q
        #pragma unroll
        for (int j = 0; j < 8; j++) {
            int col = c0 + wn*64 + j*8 + 2*tg;
            float b0v = bias[col], b1v = bias[col + 1];
            int row0 = r0 + wm*16 + g;
            float v00 = acc[j].x + b0v, v01 = acc[j].y + b1v;
            float v10 = acc[j].z + b0v, v11 = acc[j].w + b1v;
            if (act) {
                v00 = tf32f(silu_f(v00) * mult); v01 = tf32f(silu_f(v01) * mult);
                v10 = tf32f(silu_f(v10) * mult); v11 = tf32f(silu_f(v11) * mult);
            }
            *(float2*)&out[row0 * ldw + col]       = make_float2(v00, v01);
            *(float2*)&out[(row0 + 8) * ldw + col] = make_float2(v10, v11);
        }
    }
}

// ---------------- kernel 2: causal attention, diagonal-paired 64-row tiles ----------------
// grid (16, 16): block p handles m-tiles {31-p, p} (64 rows each) -> uniform 33 key-iters.
// 256 threads = 8 warps (4m x 2n). 2 CTAs/SM. dyn smem:
//   qs 64x36 | ks 2x64x36 | vts 2x32x68 | ss 64x68 = 15616 floats = 62464 B
#define ATTN_SMEM 62464
__global__ __launch_bounds__(256, 2) void attn_kernel()
{
    extern __shared__ float sm[];
    float (*qs)[36]  = (float(*)[36])sm;                 // 64 rows
    float (*ks)[36]  = (float(*)[36])(sm + 2304);        // 2*64 rows
    float (*vts)[68] = (float(*)[68])(sm + 6912);        // 2*32 rows
    float (*ss)[68]  = (float(*)[68])(sm + 11264);       // 64 rows

    const int p = blockIdx.x;                  // 0..15
    const int b = blockIdx.y >> 2, h = blockIdx.y & 3;
    const int t = threadIdx.x, w = t >> 5, lane = t & 31;
    const int wm = w & 3, wn = w >> 2;         // stage1: 4m(16r) x 2n(32c); stage2: 4m x 2d(16)
    const int g = lane >> 2, tg = lane & 3;

    const float* kp  = g_k  + (b*SEQ)*128 + h*32;
    const float* vtp = g_vt + (b*128 + h*32)*SEQ;

    const uint32 qs_u = smem_u32(&qs[0][0]);
    const uint32 ks_u = smem_u32(&ks[0][0]);
    const uint32 vt_u = smem_u32(&vts[0][0]);
    const uint32 ss_u = smem_u32(&ss[0][0]);

    // ldmatrix lane-address components
    const int lrow = lane & 7;
    const int sel4 = lane >> 3;
    const int a_ro = ((sel4 & 1) << 3) + lrow;     // row-in-16 for x4
    const int a_co = (sel4 & 2) ? 4 : 0;           // k-offset for x4
    const int l16  = lane & 15;
    const int b_ro = l16 & 7;
    const int b_co = (l16 >> 3) << 2;

    const uint32 qa = qs_u + ((wm*16 + a_ro)*36 + a_co)*4;
    const uint32 sa = ss_u + ((wm*16 + a_ro)*68 + a_co)*4;

    #pragma unroll
    for (int ph = 0; ph < 2; ph++) {
        const int tile = ph ? p : 31 - p;        // long phase first
        const int n0 = tile * 64;
        const float* qp = g_q + (b*SEQ + n0)*128 + h*32;

        // q tile: 64 rows x 32 floats (512 float4)
        #pragma unroll
        for (int c = t; c < 512; c += 256) {
            int r = c >> 3, s = (c & 7) << 2;
            cp16(qs_u + (r*36 + s)*4, qp + r*128 + s);
        }
        // first k/vt tile
        #pragma unroll
        for (int c = t; c < 512; c += 256) {
            int r = c >> 3, s = (c & 7) << 2;
            cp16(ks_u + (r*36 + s)*4, kp + r*128 + s);
        }
        #pragma unroll
        for (int c = t; c < 512; c += 256) {
            int r = c >> 4, s = (c & 15) << 2;
            cp16(vt_u + (r*68 + s)*4, vtp + r*SEQ + s);
        }
        CP_COMMIT();

        float4 acc2[2];
        acc2[0] = make_float4(0.f, 0.f, 0.f, 0.f);
        acc2[1] = make_float4(0.f, 0.f, 0.f, 0.f);

        const int iters = tile + 1;
        for (int it = 0; it < iters; ++it) {
            const int m0 = it * 64;
            const int buf = it & 1;
            if (it + 1 < iters) {
                const int m1 = m0 + 64, nb = buf ^ 1;
                #pragma unroll
                for (int c = t; c < 512; c += 256) {
                    int r = c >> 3, s = (c & 7) << 2;
                    cp16(ks_u + ((nb*64 + r)*36 + s)*4, kp + (m1 + r)*128 + s);
                }
                #pragma unroll
                for (int c = t; c < 512; c += 256) {
                    int r = c >> 4, s = (c & 15) << 2;
                    cp16(vt_u + ((nb*32 + r)*68 + s)*4, vtp + r*SEQ + m1 + s);
                }
                CP_COMMIT();
                CP_WAIT1();
            } else {
                CP_WAIT0();
            }
            __syncthreads();

            // ---- stage 1: scores 64x64 (warp m16 x n32)
            float4 sc[4];
            #pragma unroll
            for (int j = 0; j < 4; j++) sc[j] = make_float4(0.f, 0.f, 0.f, 0.f);

            const uint32 kb = ks_u + (uint32)buf*64*36*4 + ((wn*32 + b_ro)*36 + b_co)*4;
            #pragma unroll
            for (int kk = 0; kk < 32; kk += 8) {
                uint32 A[4];
                ldsm_x4(A[0], A[1], A[2], A[3], qa + kk*4);
                #pragma unroll
                for (int j = 0; j < 4; j++) {
                    uint32 b0, b1;
                    ldsm_x2(b0, b1, kb + (j*8*36 + kk)*4);
                    mma_tf32(sc[j], A[0], A[1], A[2], A[3], b0, b1);
                }
            }

            // mask + square + silu(tanh) -> ss (tf32)
            {
                const int lr = wm*16 + g;
                const int nrow0 = n0 + lr, nrow1 = nrow0 + 8;
                #pragma unroll
                for (int j = 0; j < 4; j++) {
                    const int lc = wn*32 + j*8 + 2*tg;
                    const int cc = m0 + lc;
                    float s;
                    s = sc[j].x; s = (cc     <= nrow0) ? s*s : 0.f; float w00 = tf32f(silu_t(s));
                    s = sc[j].y; s = (cc + 1 <= nrow0) ? s*s : 0.f; float w01 = tf32f(silu_t(s));
                    s = sc[j].z; s = (cc     <= nrow1) ? s*s : 0.f; float w10 = tf32f(silu_t(s));
                    s = sc[j].w; s = (cc + 1 <= nrow1) ? s*s : 0.f; float w11 = tf32f(silu_t(s));
                    *(float2*)&ss[lr    ][lc] = make_float2(w00, w01);
                    *(float2*)&ss[lr + 8][lc] = make_float2(w10, w11);
                }
            }
            __syncthreads();

            // ---- stage 2: acc2 += ss @ v  (warp m16 x d16)
            const uint32 vb = vt_u + (uint32)buf*32*68*4 + ((wn*16 + b_ro)*68 + b_co)*4;
            #pragma unroll
            for (int kk = 0; kk < 64; kk += 8) {
                uint32 A[4];
                ldsm_x4(A[0], A[1], A[2], A[3], sa + kk*4);
                #pragma unroll
                for (int j = 0; j < 2; j++) {
                    uint32 b0, b1;
                    ldsm_x2(b0, b1, vb + (j*8*68 + kk)*4);
                    mma_tf32(acc2[j], A[0], A[1], A[2], A[3], b0, b1);
                }
            }
            __syncthreads();
        }

        {
            const int row0 = n0 + wm*16 + g;
            #pragma unroll
            for (int j = 0; j < 2; j++) {
                const int col = h*32 + wn*16 + j*8 + 2*tg;
                *(float2*)&g_sattn[(b*SEQ + row0    )*128 + col] = make_float2(acc2[j].x, acc2[j].y);
                *(float2*)&g_sattn[(b*SEQ + row0 + 8)*128 + col] = make_float2(acc2[j].z, acc2[j].w);
            }
        }
    }
}

// ---------------- kernel 3: relative-position attention ----------------
// grid (32, 2, 4): n-tile 64, d-tile 64, batch. 8 warps = 2n x 4d (warp n32 x d16).
// Toeplitz A fragments via scalar LDS; V B-fragments via ldmatrix; cp.async pipeline.
// dyn smem: swl 4096 | vts 2x64x68 = 51200 B
#define POS_SMEM 51200
__global__ __launch_bounds__(256, 2) void pos_kernel(const float* __restrict__ pos_w)
{
    extern __shared__ float sm[];
    float* swl = sm;                                   // 4096 (tf32-rounded pos_w)
    float (*vts)[68] = (float(*)[68])(sm + 4096);      // 2*64 rows

    const int n0 = blockIdx.x * 64;
    const int d0 = blockIdx.y * 64;
    const int b  = blockIdx.z;
    const int t = threadIdx.x, w = t >> 5, lane = t & 31;
    const int wmn = w & 1, wd = w >> 1;     // 2 n-groups (n32), 4 d-groups (d16)
    const int g = lane >> 2, tg = lane & 3;

    const int l16  = lane & 15;
    const int b_ro = l16 & 7;
    const int b_co = (l16 >> 3) << 2;

    const uint32 vt_u = smem_u32(&vts[0][0]);
    const float* vtp = g_vt + (b*128 + d0)*SEQ;

    for (int i = t; i < 4095; i += 256) swl[i] = tf32f(pos_w[i]);
    if (t == 0) swl[4095] = 0.f;

    // first vt tile: 64 rows x 64 floats
    #pragma unroll
    for (int c = t; c < 1024; c += 256) {
        int r = c >> 4, s = (c & 15) << 2;
        cp16(vt_u + (r*68 + s)*4, vtp + r*SEQ + s);
    }
    CP_COMMIT();

    float4 acc[2][2];
    #pragma unroll
    for (int mi = 0; mi < 2; mi++)
        #pragma unroll
        for (int j = 0; j < 2; j++) acc[mi][j] = make_float4(0.f, 0.f, 0.f, 0.f);

    // A element (row r, col c) = swl[2047 + m0 + c - n0 - r]
    const int abase = 2047 - n0 - wmn*32 - g + tg;

    for (int it = 0; it < 32; ++it) {
        const int m0 = it * 64;
        const int buf = it & 1;
        if (it < 31) {
            const int m1 = m0 + 64, nb = buf ^ 1;
            #pragma unroll
            for (int c = t; c < 1024; c += 256) {
                int r = c >> 4, s = (c & 15) << 2;
                cp16(vt_u + ((nb*64 + r)*68 + s)*4, vtp + r*SEQ + m1 + s);
            }
            CP_COMMIT();
            CP_WAIT1();
        } else {
            CP_WAIT0();
        }
        __syncthreads();

        const uint32 vb = vt_u + (uint32)buf*64*68*4 + ((wd*16 + b_ro)*68 + b_co)*4;
        const float* ab = swl + abase + m0;
        #pragma unroll
        for (int kk = 0; kk < 64; kk += 8) {
            uint32 A0[4], A1[4];
            {
                const float* pp = ab + kk;         // rows wmn*32 + {g, g+8}
                A0[0] = fb(pp[0]);   A0[1] = fb(pp[-8]);
                A0[2] = fb(pp[4]);   A0[3] = fb(pp[-4]);
                const float* qq = pp - 16;         // rows +16
                A1[0] = fb(qq[0]);   A1[1] = fb(qq[-8]);
                A1[2] = fb(qq[4]);   A1[3] = fb(qq[-4]);
            }
            #pragma unroll
            for (int j = 0; j < 2; j++) {
                uint32 b0, b1;
                ldsm_x2(b0, b1, vb + (j*8*68 + kk)*4);
                mma_tf32(acc[0][j], A0[0], A0[1], A0[2], A0[3], b0, b1);
                mma_tf32(acc[1][j], A1[0], A1[1], A1[2], A1[3], b0, b1);
            }
        }
        __syncthreads();
    }

    #pragma unroll
    for (int mi = 0; mi < 2; mi++) {
        const int row0 = n0 + wmn*32 + mi*16 + g;
        #pragma unroll
        for (int j = 0; j < 2; j++) {
            const int col = d0 + wd*16 + j*8 + 2*tg;
            *(float2*)&g_pattn[(b*SEQ + row0    )*128 + col] = make_float2(acc[mi][j].x, acc[mi][j].y);
            *(float2*)&g_pattn[(b*SEQ + row0 + 8)*128 + col] = make_float2(acc[mi][j].z, acc[mi][j].w);
        }
    }
}

// ---------------- kernel 4: fused LayerNorm + final GEMM + relu + residual ----------------
// grid 256, 256 threads. smem: as[32][264] (8448 f) + ws[32][128] (4096 f) = 50176 B
#define FIN_SMEM 50176
__device__ __forceinline__ ull pack2(float lo, float hi) {
    ull r;
    asm("mov.b64 %0, {%1, %2};" : "=l"(r) : "r"(__float_as_uint(lo)), "r"(__float_as_uint(hi)));
    return r;
}
__device__ __forceinline__ ull fma2(ull a, ull b, ull c) {
    ull d;
    asm("fma.rn.f32x2 %0, %1, %2, %3;" : "=l"(d) : "l"(a), "l"(b), "l"(c));
    return d;
}
__device__ __forceinline__ float2 unpack2(ull v) {
    unsigned lo, hi;
    asm("mov.b64 {%0, %1}, %2;" : "=r"(lo), "=r"(hi) : "l"(v));
    return make_float2(__uint_as_float(lo), __uint_as_float(hi));
}

__global__ __launch_bounds__(256) void final_kernel(const float* __restrict__ x,
                                                    const float* __restrict__ Wf,
                                                    const float* __restrict__ bf,
                                                    const float* __restrict__ gamma,
                                                    const float* __restrict__ beta,
                                                    float* __restrict__ out)
{
    extern __shared__ float sm[];
    float (*as)[264] = (float(*)[264])sm;            // 32 rows, cols 0..255 = [sattn|pattn]
    float (*ws)[128] = (float(*)[128])(sm + 32*264);

    const int r0 = blockIdx.x * 32;
    const int t  = threadIdx.x;
    const uint32 as_u = smem_u32(&as[0][0]);

    // load concat(sattn, pattn): 32 rows x 256 floats = 2048 float4
    #pragma unroll
    for (int i = t; i < 2048; i += 256) {
        int r = i >> 6, c4 = i & 63;
        const float* src = (c4 < 32) ? &g_sattn[(r0 + r)*128 + c4*4]
                                     : &g_pattn[(r0 + r)*128 + (c4 - 32)*4];
        cp16(as_u + (r*264 + c4*4)*4, src);
    }
    CP_COMMIT(); CP_WAIT0();
    __syncthreads();

    // ---- LayerNorm: 8 threads per row, 32 cols each ----
    const int r = t >> 3, sub = t & 7;
    float vals[32];
    #pragma unroll
    for (int k4 = 0; k4 < 8; k4++) {
        float4 v = *(const float4*)&as[r][sub*32 + k4*4];
        vals[k4*4+0] = v.x; vals[k4*4+1] = v.y; vals[k4*4+2] = v.z; vals[k4*4+3] = v.w;
    }
    float sum = 0.f, sq = 0.f;
    #pragma unroll
    for (int k = 0; k < 32; k++) { sum += vals[k]; sq = fmaf(vals[k], vals[k], sq); }
    #pragma unroll
    for (int o = 1; o < 8; o <<= 1) {
        sum += __shfl_xor_sync(0xffffffffu, sum, o);
        sq  += __shfl_xor_sync(0xffffffffu, sq, o);
    }
    const float mean = sum * (1.f / 256.f);
    const float var  = sq * (1.f / 256.f) - mean * mean;
    const float rstd = rsqrtf(var + 1e-3f);

    #pragma unroll
    for (int k4 = 0; k4 < 8; k4++) {
        const int c = sub*32 + k4*4;
        float4 ga = *(const float4*)&gamma[c];
        float4 be = *(const float4*)&beta[c];
        float4 uu = *(const float4*)&g_u[(r0 + r)*256 + c];
        float4 o;
        o.x = uu.x * ((vals[k4*4+0] - mean) * rstd * ga.x + be.x);
        o.y = uu.y * ((vals[k4*4+1] - mean) * rstd * ga.y + be.y);
        o.z = uu.z * ((vals[k4*4+2] - mean) * rstd * ga.z + be.z);
        o.w = uu.w * ((vals[k4*4+3] - mean) * rstd * ga.w + be.w);
        *(float4*)&as[r][c] = o;
    }
    __syncthreads();

    // ---- GEMM 32x256 @ Wf[256,128] (f32x2), relu, +x ----
    const int ty = t >> 5, tx = t & 31;
    ull acc[4][2];
    #pragma unroll
    for (int i = 0; i < 4; i++) { acc[i][0] = 0ull; acc[i][1] = 0ull; }

    for (int kc = 0; kc < 256; kc += 32) {
        #pragma unroll
        for (int i = t; i < 32*128; i += 256) {
            int rr = i >> 7, cc = i & 127;
            ws[rr][cc] = Wf[(kc + rr) * 128 + cc];
        }
        __syncthreads();

        #pragma unroll
        for (int kk = 0; kk < 32; kk += 4) {
            float4 a[4];
            #pragma unroll
            for (int i = 0; i < 4; i++)
                a[i] = *(const float4*)&as[ty*4 + i][kc + kk];
            #pragma unroll
            for (int q = 0; q < 4; q++) {
                ulonglong2 bp = *(const ulonglong2*)&ws[kk + q][tx*4];
                #pragma unroll
                for (int i = 0; i < 4; i++) {
                    float av = (q == 0) ? a[i].x : (q == 1) ? a[i].y : (q == 2) ? a[i].z : a[i].w;
                    ull ap = pack2(av, av);
                    acc[i][0] = fma2(ap, bp.x, acc[i][0]);
                    acc[i][1] = fma2(ap, bp.y, acc[i][1]);
                }
            }
        }
        __syncthreads();
    }

    #pragma unroll
    for (int i = 0; i < 4; i++) {
        int row = r0 + ty*4 + i;
        float2 p0 = unpack2(acc[i][0]);
        float2 p1 = unpack2(acc[i][1]);
        float o[4] = {p0.x, p0.y, p1.x, p1.y};
        float4 xr = *(const float4*)&x[row * 128 + tx*4];
        float xv[4] = {xr.x, xr.y, xr.z, xr.w};
        float4 res;
        float* rp = (float*)&res;
        #pragma unroll
        for (int j = 0; j < 4; j++) {
            int c = tx*4 + j;
            rp[j] = fmaxf(o[j] + bf[c], 0.f) + xv[j];
        }
        *(float4*)&out[row * 128 + tx*4] = res;
    }
}

// ---------------- launcher ----------------
extern "C" void kernel_launch(void* const* d_in, const int* in_sizes, int n_in,
                              void* d_out, int out_size)
{
    const float* x      = (const float*)d_in[0];
    const float* Wq     = (const float*)d_in[1];
    const float* bq     = (const float*)d_in[2];
    const float* Wk     = (const float*)d_in[3];
    const float* bk     = (const float*)d_in[4];
    const float* Wv     = (const float*)d_in[5];
    const float* bv     = (const float*)d_in[6];
    const float* Wu     = (const float*)d_in[7];
    const float* bu     = (const float*)d_in[8];
    const float* pos_w  = (const float*)d_in[9];
    const float* gamma  = (const float*)d_in[10];
    const float* beta   = (const float*)d_in[11];
    const float* Wf     = (const float*)d_in[12];
    const float* bf     = (const float*)d_in[13];
    float* out = (float*)d_out;

    cudaFuncSetAttribute(attn_kernel,  cudaFuncAttributeMaxDynamicSharedMemorySize, ATTN_SMEM);
    cudaFuncSetAttribute(pos_kernel,   cudaFuncAttributeMaxDynamicSharedMemorySize, POS_SMEM);
    cudaFuncSetAttribute(final_kernel, cudaFuncAttributeMaxDynamicSharedMemorySize, FIN_SMEM);

    proj_kernel<<<dim3(5, ROWS/64), 256>>>(x, Wq, bq, Wk, bk, Wv, bv, Wu, bu);
    attn_kernel<<<dim3(16, BATCH*4), 256, ATTN_SMEM>>>();
    pos_kernel<<<dim3(SEQ/64, 2, BATCH), 256, POS_SMEM>>>(pos_w);
    final_kernel<<<ROWS/32, 256, FIN_SMEM>>>(x, Wf, bf, gamma, beta, out);
}

// round 8
// speedup vs baseline: 1.6899x; 1.1248x over previous
#include <cuda_runtime.h>
#include <math.h>

#define BATCH 4
#define SEQ   2048
#define DIM   128
#define ROWS  (BATCH*SEQ)   // 8192

typedef unsigned long long ull;
typedef unsigned int uint32;

// ---------------- scratch (no allocation allowed) ----------------
__device__ float g_q[ROWS*DIM];       // tf32-rounded, PRE-SCALED by 1/sqrt(32)
__device__ float g_k[ROWS*DIM];       // tf32-rounded
__device__ float g_vt[ROWS*DIM];      // tf32-rounded, TRANSPOSED: [b][d=128][token=2048]
__device__ float g_u[ROWS*2*DIM];     // full f32
__device__ float g_sattn[ROWS*DIM];
__device__ float g_pattn[ROWS*DIM];

__device__ __forceinline__ float silu_f(float v) {
    return v * (1.f / (1.f + __expf(-v)));
}
__device__ __forceinline__ float tanh_ap(float x) {
    float y; asm("tanh.approx.f32 %0, %1;" : "=f"(y) : "f"(x)); return y;
}
// silu via 1 MUFU: x*sigmoid(x) = x*(0.5*tanh(0.5x)+0.5)
__device__ __forceinline__ float silu_t(float x) {
    return fmaf(x, 0.5f * tanh_ap(0.5f * x), 0.5f * x);
}
__device__ __forceinline__ uint32 tf32_of(float f) {
    uint32 u; asm("cvt.rna.tf32.f32 %0, %1;" : "=r"(u) : "f"(f)); return u;
}
__device__ __forceinline__ float tf32f(float f) { return __uint_as_float(tf32_of(f)); }
__device__ __forceinline__ uint32 fb(float f) { return __float_as_uint(f); }
__device__ __forceinline__ uint32 smem_u32(const void* p) {
    return (uint32)__cvta_generic_to_shared(p);
}

__device__ __forceinline__ void mma_tf32(float4& d, uint32 a0, uint32 a1, uint32 a2, uint32 a3,
                                         uint32 b0, uint32 b1) {
    asm volatile(
        "mma.sync.aligned.m16n8k8.row.col.f32.tf32.tf32.f32 "
        "{%0,%1,%2,%3}, {%4,%5,%6,%7}, {%8,%9}, {%0,%1,%2,%3};"
        : "+f"(d.x), "+f"(d.y), "+f"(d.z), "+f"(d.w)
        : "r"(a0), "r"(a1), "r"(a2), "r"(a3), "r"(b0), "r"(b1));
}
__device__ __forceinline__ void ldsm_x4(uint32& r0, uint32& r1, uint32& r2, uint32& r3, uint32 addr) {
    asm volatile("ldmatrix.sync.aligned.m8n8.x4.shared.b16 {%0,%1,%2,%3}, [%4];"
        : "=r"(r0), "=r"(r1), "=r"(r2), "=r"(r3) : "r"(addr));
}
__device__ __forceinline__ void ldsm_x2(uint32& r0, uint32& r1, uint32 addr) {
    asm volatile("ldmatrix.sync.aligned.m8n8.x2.shared.b16 {%0,%1}, [%2];"
        : "=r"(r0), "=r"(r1) : "r"(addr));
}
__device__ __forceinline__ void cp16(uint32 dst, const float* src) {
    asm volatile("cp.async.ca.shared.global [%0], [%1], 16;" :: "r"(dst), "l"(src));
}
#define CP_COMMIT() asm volatile("cp.async.commit_group;")
#define CP_WAIT1()  asm volatile("cp.async.wait_group 1;")
#define CP_WAIT0()  asm volatile("cp.async.wait_group 0;")

// ---------------- kernel 1: fused q/k/v/u projections (tf32 mma) ----------------
// grid (5, 128). seg 0=q (pre-scaled 1/sqrt(32)), 1=k, 2=v(transposed out), 3/4=u halves.
__global__ __launch_bounds__(256) void proj_kernel(
    const float* __restrict__ x,
    const float* __restrict__ Wq, const float* __restrict__ bq,
    const float* __restrict__ Wk, const float* __restrict__ bk,
    const float* __restrict__ Wv, const float* __restrict__ bv,
    const float* __restrict__ Wu, const float* __restrict__ bu)
{
    __shared__ float xs[64][36];
    __shared__ float ws[32][136];

    const int seg = blockIdx.x;
    const int r0  = blockIdx.y * 64;

    const float* W; const float* bias; int ldw, c0;
    if (seg == 0)      { W = Wq; bias = bq; ldw = 128; c0 = 0; }
    else if (seg == 1) { W = Wk; bias = bk; ldw = 128; c0 = 0; }
    else if (seg == 2) { W = Wv; bias = bv; ldw = 128; c0 = 0; }
    else               { W = Wu; bias = bu; ldw = 256; c0 = (seg - 3) * 128; }

    const int t = threadIdx.x;
    const int w = t >> 5, lane = t & 31;
    const int wm = w & 3, wn = w >> 2;
    const int g = lane >> 2, tg = lane & 3;

    float4 acc[8];
    #pragma unroll
    for (int j = 0; j < 8; j++) acc[j] = make_float4(0.f, 0.f, 0.f, 0.f);

    for (int kc = 0; kc < 128; kc += 32) {
        #pragma unroll
        for (int i = t*4; i < 64*32; i += 256*4) {
            int rr = i >> 5, cc = i & 31;
            float4 v4 = *(const float4*)&x[(r0 + rr) * 128 + kc + cc];
            xs[rr][cc+0] = tf32f(v4.x); xs[rr][cc+1] = tf32f(v4.y);
            xs[rr][cc+2] = tf32f(v4.z); xs[rr][cc+3] = tf32f(v4.w);
        }
        #pragma unroll
        for (int i = t*4; i < 32*128; i += 256*4) {
            int rr = i >> 7, cc = i & 127;
            float4 v4 = *(const float4*)&W[(kc + rr) * ldw + c0 + cc];
            ws[rr][cc+0] = tf32f(v4.x); ws[rr][cc+1] = tf32f(v4.y);
            ws[rr][cc+2] = tf32f(v4.z); ws[rr][cc+3] = tf32f(v4.w);
        }
        __syncthreads();

        #pragma unroll
        for (int kk = 0; kk < 32; kk += 8) {
            uint32 a0 = fb(xs[wm*16 + g    ][kk + tg    ]);
            uint32 a1 = fb(xs[wm*16 + g + 8][kk + tg    ]);
            uint32 a2 = fb(xs[wm*16 + g    ][kk + tg + 4]);
            uint32 a3 = fb(xs[wm*16 + g + 8][kk + tg + 4]);
            #pragma unroll
            for (int j = 0; j < 8; j++) {
                uint32 b0 = fb(ws[kk + tg    ][wn*64 + j*8 + g]);
                uint32 b1 = fb(ws[kk + tg + 4][wn*64 + j*8 + g]);
                mma_tf32(acc[j], a0, a1, a2, a3, b0, b1);
            }
        }
        __syncthreads();
    }

    if (seg == 2) {
        // v: transposed tf32 store into g_vt[b][d][token]
        const int bb = r0 >> 11;
        const int tok = (r0 & 2047) + wm*16 + g;
        #pragma unroll
        for (int j = 0; j < 8; j++) {
            int col = wn*64 + j*8 + 2*tg;
            float b0v = bias[col], b1v = bias[col + 1];
            float v00 = tf32f(silu_f(acc[j].x + b0v));
            float v01 = tf32f(silu_f(acc[j].y + b1v));
            float v10 = tf32f(silu_f(acc[j].z + b0v));
            float v11 = tf32f(silu_f(acc[j].w + b1v));
            float* p0 = &g_vt[(bb*128 + col) * SEQ + tok];
            p0[0] = v00; p0[8] = v10;
            float* p1 = p0 + SEQ;
            p1[0] = v01; p1[8] = v11;
        }
    } else {
        float* out = (seg == 0) ? g_q : (seg == 1) ? g_k : g_u;
        bool act = (seg <= 1);
        const float mult = (seg == 0) ? 0.17677669529663687f : 1.0f;  // 1/sqrt(32) into q
        #pragma unroll
        for (int j = 0; j < 8; j++) {
            int col = c0 + wn*64 + j*8 + 2*tg;
            float b0v = bias[col], b1v = bias[col + 1];
            int row0 = r0 + wm*16 + g;
            float v00 = acc[j].x + b0v, v01 = acc[j].y + b1v;
            float v10 = acc[j].z + b0v, v11 = acc[j].w + b1v;
            if (act) {
                v00 = tf32f(silu_f(v00) * mult); v01 = tf32f(silu_f(v01) * mult);
                v10 = tf32f(silu_f(v10) * mult); v11 = tf32f(silu_f(v11) * mult);
            }
            *(float2*)&out[row0 * ldw + col]       = make_float2(v00, v01);
            *(float2*)&out[(row0 + 8) * ldw + col] = make_float2(v10, v11);
        }
    }
}

// ---------------- kernel 2: causal attention, diagonal-paired 64-row tiles ----------------
// grid (16, 16): block p handles m-tiles {31-p, p} (64 rows each) -> uniform 33 key-iters.
// 256 threads = 8 warps (4m x 2n). 2 CTAs/SM. dyn smem:
//   qs 64x36 | ks 2x64x36 | vts 2x32x68 | ss 64x68 = 15616 floats = 62464 B
#define ATTN_SMEM 62464
__global__ __launch_bounds__(256, 2) void attn_kernel()
{
    extern __shared__ float sm[];
    float (*qs)[36]  = (float(*)[36])sm;                 // 64 rows
    float (*ks)[36]  = (float(*)[36])(sm + 2304);        // 2*64 rows
    float (*vts)[68] = (float(*)[68])(sm + 6912);        // 2*32 rows
    float (*ss)[68]  = (float(*)[68])(sm + 11264);       // 64 rows

    const int p = blockIdx.x;                  // 0..15
    const int b = blockIdx.y >> 2, h = blockIdx.y & 3;
    const int t = threadIdx.x, w = t >> 5, lane = t & 31;
    const int wm = w & 3, wn = w >> 2;
    const int g = lane >> 2, tg = lane & 3;

    const float* kp  = g_k  + (b*SEQ)*128 + h*32;
    const float* vtp = g_vt + (b*128 + h*32)*SEQ;

    const uint32 qs_u = smem_u32(&qs[0][0]);
    const uint32 ks_u = smem_u32(&ks[0][0]);
    const uint32 vt_u = smem_u32(&vts[0][0]);
    const uint32 ss_u = smem_u32(&ss[0][0]);

    // ldmatrix lane-address components
    const int lrow = lane & 7;
    const int sel4 = lane >> 3;
    const int a_ro = ((sel4 & 1) << 3) + lrow;
    const int a_co = (sel4 & 2) ? 4 : 0;
    const int l16  = lane & 15;
    const int b_ro = l16 & 7;
    const int b_co = (l16 >> 3) << 2;

    const uint32 qa = qs_u + ((wm*16 + a_ro)*36 + a_co)*4;
    const uint32 sa = ss_u + ((wm*16 + a_ro)*68 + a_co)*4;

    #pragma unroll
    for (int ph = 0; ph < 2; ph++) {
        const int tile = ph ? p : 31 - p;        // long phase first
        const int n0 = tile * 64;
        const float* qp = g_q + (b*SEQ + n0)*128 + h*32;

        #pragma unroll
        for (int c = t; c < 512; c += 256) {
            int r = c >> 3, s = (c & 7) << 2;
            cp16(qs_u + (r*36 + s)*4, qp + r*128 + s);
        }
        #pragma unroll
        for (int c = t; c < 512; c += 256) {
            int r = c >> 3, s = (c & 7) << 2;
            cp16(ks_u + (r*36 + s)*4, kp + r*128 + s);
        }
        #pragma unroll
        for (int c = t; c < 512; c += 256) {
            int r = c >> 4, s = (c & 15) << 2;
            cp16(vt_u + (r*68 + s)*4, vtp + r*SEQ + s);
        }
        CP_COMMIT();

        float4 acc2[2];
        acc2[0] = make_float4(0.f, 0.f, 0.f, 0.f);
        acc2[1] = make_float4(0.f, 0.f, 0.f, 0.f);

        const int iters = tile + 1;
        for (int it = 0; it < iters; ++it) {
            const int m0 = it * 64;
            const int buf = it & 1;
            if (it + 1 < iters) {
                const int m1 = m0 + 64, nb = buf ^ 1;
                #pragma unroll
                for (int c = t; c < 512; c += 256) {
                    int r = c >> 3, s = (c & 7) << 2;
                    cp16(ks_u + ((nb*64 + r)*36 + s)*4, kp + (m1 + r)*128 + s);
                }
                #pragma unroll
                for (int c = t; c < 512; c += 256) {
                    int r = c >> 4, s = (c & 15) << 2;
                    cp16(vt_u + ((nb*32 + r)*68 + s)*4, vtp + r*SEQ + m1 + s);
                }
                CP_COMMIT();
                CP_WAIT1();
            } else {
                CP_WAIT0();
            }
            __syncthreads();

            // ---- stage 1: scores 64x64 (warp m16 x n32)
            float4 sc[4];
            #pragma unroll
            for (int j = 0; j < 4; j++) sc[j] = make_float4(0.f, 0.f, 0.f, 0.f);

            const uint32 kb = ks_u + (uint32)buf*64*36*4 + ((wn*32 + b_ro)*36 + b_co)*4;
            #pragma unroll
            for (int kk = 0; kk < 32; kk += 8) {
                uint32 A[4];
                ldsm_x4(A[0], A[1], A[2], A[3], qa + kk*4);
                #pragma unroll
                for (int j = 0; j < 4; j++) {
                    uint32 b0, b1;
                    ldsm_x2(b0, b1, kb + (j*8*36 + kk)*4);
                    mma_tf32(sc[j], A[0], A[1], A[2], A[3], b0, b1);
                }
            }

            // mask + square + silu(tanh) -> ss (tf32)
            {
                const int lr = wm*16 + g;
                const int nrow0 = n0 + lr, nrow1 = nrow0 + 8;
                #pragma unroll
                for (int j = 0; j < 4; j++) {
                    const int lc = wn*32 + j*8 + 2*tg;
                    const int cc = m0 + lc;
                    float s;
                    s = sc[j].x; s = (cc     <= nrow0) ? s*s : 0.f; float w00 = tf32f(silu_t(s));
                    s = sc[j].y; s = (cc + 1 <= nrow0) ? s*s : 0.f; float w01 = tf32f(silu_t(s));
                    s = sc[j].z; s = (cc     <= nrow1) ? s*s : 0.f; float w10 = tf32f(silu_t(s));
                    s = sc[j].w; s = (cc + 1 <= nrow1) ? s*s : 0.f; float w11 = tf32f(silu_t(s));
                    *(float2*)&ss[lr    ][lc] = make_float2(w00, w01);
                    *(float2*)&ss[lr + 8][lc] = make_float2(w10, w11);
                }
            }
            __syncthreads();

            // ---- stage 2: acc2 += ss @ v  (warp m16 x d16)
            const uint32 vb = vt_u + (uint32)buf*32*68*4 + ((wn*16 + b_ro)*68 + b_co)*4;
            #pragma unroll
            for (int kk = 0; kk < 64; kk += 8) {
                uint32 A[4];
                ldsm_x4(A[0], A[1], A[2], A[3], sa + kk*4);
                #pragma unroll
                for (int j = 0; j < 2; j++) {
                    uint32 b0, b1;
                    ldsm_x2(b0, b1, vb + (j*8*68 + kk)*4);
                    mma_tf32(acc2[j], A[0], A[1], A[2], A[3], b0, b1);
                }
            }
            __syncthreads();
        }

        {
            const int row0 = n0 + wm*16 + g;
            #pragma unroll
            for (int j = 0; j < 2; j++) {
                const int col = h*32 + wn*16 + j*8 + 2*tg;
                *(float2*)&g_sattn[(b*SEQ + row0    )*128 + col] = make_float2(acc2[j].x, acc2[j].y);
                *(float2*)&g_sattn[(b*SEQ + row0 + 8)*128 + col] = make_float2(acc2[j].z, acc2[j].w);
            }
        }
    }
}

// ---------------- kernel 3: relative-position attention ----------------
// grid (32, 2, 4). Toeplitz A via scalar LDS; V via ldmatrix; cp.async pipeline.
#define POS_SMEM 51200
__global__ __launch_bounds__(256, 2) void pos_kernel(const float* __restrict__ pos_w)
{
    extern __shared__ float sm[];
    float* swl = sm;                                   // 4096 (tf32-rounded pos_w)
    float (*vts)[68] = (float(*)[68])(sm + 4096);      // 2*64 rows

    const int n0 = blockIdx.x * 64;
    const int d0 = blockIdx.y * 64;
    const int b  = blockIdx.z;
    const int t = threadIdx.x, w = t >> 5, lane = t & 31;
    const int wmn = w & 1, wd = w >> 1;
    const int g = lane >> 2, tg = lane & 3;

    const int l16  = lane & 15;
    const int b_ro = l16 & 7;
    const int b_co = (l16 >> 3) << 2;

    const uint32 vt_u = smem_u32(&vts[0][0]);
    const float* vtp = g_vt + (b*128 + d0)*SEQ;

    for (int i = t; i < 4095; i += 256) swl[i] = tf32f(pos_w[i]);
    if (t == 0) swl[4095] = 0.f;

    #pragma unroll
    for (int c = t; c < 1024; c += 256) {
        int r = c >> 4, s = (c & 15) << 2;
        cp16(vt_u + (r*68 + s)*4, vtp + r*SEQ + s);
    }
    CP_COMMIT();

    float4 acc[2][2];
    #pragma unroll
    for (int mi = 0; mi < 2; mi++)
        #pragma unroll
        for (int j = 0; j < 2; j++) acc[mi][j] = make_float4(0.f, 0.f, 0.f, 0.f);

    const int abase = 2047 - n0 - wmn*32 - g + tg;

    for (int it = 0; it < 32; ++it) {
        const int m0 = it * 64;
        const int buf = it & 1;
        if (it < 31) {
            const int m1 = m0 + 64, nb = buf ^ 1;
            #pragma unroll
            for (int c = t; c < 1024; c += 256) {
                int r = c >> 4, s = (c & 15) << 2;
                cp16(vt_u + ((nb*64 + r)*68 + s)*4, vtp + r*SEQ + m1 + s);
            }
            CP_COMMIT();
            CP_WAIT1();
        } else {
            CP_WAIT0();
        }
        __syncthreads();

        const uint32 vb = vt_u + (uint32)buf*64*68*4 + ((wd*16 + b_ro)*68 + b_co)*4;
        const float* ab = swl + abase + m0;
        #pragma unroll
        for (int kk = 0; kk < 64; kk += 8) {
            uint32 A0[4], A1[4];
            {
                const float* pp = ab + kk;
                A0[0] = fb(pp[0]);   A0[1] = fb(pp[-8]);
                A0[2] = fb(pp[4]);   A0[3] = fb(pp[-4]);
                const float* qq = pp - 16;
                A1[0] = fb(qq[0]);   A1[1] = fb(qq[-8]);
                A1[2] = fb(qq[4]);   A1[3] = fb(qq[-4]);
            }
            #pragma unroll
            for (int j = 0; j < 2; j++) {
                uint32 b0, b1;
                ldsm_x2(b0, b1, vb + (j*8*68 + kk)*4);
                mma_tf32(acc[0][j], A0[0], A0[1], A0[2], A0[3], b0, b1);
                mma_tf32(acc[1][j], A1[0], A1[1], A1[2], A1[3], b0, b1);
            }
        }
        __syncthreads();
    }

    #pragma unroll
    for (int mi = 0; mi < 2; mi++) {
        const int row0 = n0 + wmn*32 + mi*16 + g;
        #pragma unroll
        for (int j = 0; j < 2; j++) {
            const int col = d0 + wd*16 + j*8 + 2*tg;
            *(float2*)&g_pattn[(b*SEQ + row0    )*128 + col] = make_float2(acc[mi][j].x, acc[mi][j].y);
            *(float2*)&g_pattn[(b*SEQ + row0 + 8)*128 + col] = make_float2(acc[mi][j].z, acc[mi][j].w);
        }
    }
}

// ---------------- kernel 4: fused LN + final GEMM (tf32 mma) + relu + residual ----------------
// grid 256, 256 threads = 8 warps (2m x 4n), warp m16 x n32. Block: 32 rows x 128 cols.
// smem: as[32][260] (33280 B) + ws[32][136] (17408 B) = 50688 B
#define FIN_SMEM 50688
__global__ __launch_bounds__(256) void final_kernel(const float* __restrict__ x,
                                                    const float* __restrict__ Wf,
                                                    const float* __restrict__ bf,
                                                    const float* __restrict__ gamma,
                                                    const float* __restrict__ beta,
                                                    float* __restrict__ out)
{
    extern __shared__ float sm[];
    float (*as)[260] = (float(*)[260])sm;            // 32 rows, cols 0..255 = [sattn|pattn]
    float (*ws)[136] = (float(*)[136])(sm + 32*260);

    const int r0 = blockIdx.x * 32;
    const int t  = threadIdx.x;
    const uint32 as_u = smem_u32(&as[0][0]);

    // load concat(sattn, pattn): 32 rows x 256 floats = 2048 float4
    #pragma unroll
    for (int i = t; i < 2048; i += 256) {
        int r = i >> 6, c4 = i & 63;
        const float* src = (c4 < 32) ? &g_sattn[(r0 + r)*128 + c4*4]
                                     : &g_pattn[(r0 + r)*128 + (c4 - 32)*4];
        cp16(as_u + (r*260 + c4*4)*4, src);
    }
    CP_COMMIT(); CP_WAIT0();
    __syncthreads();

    // ---- LayerNorm: 8 threads/row; thread covers cols {sub*4 + k4*32} (bank-conflict-free)
    {
        const int r = t >> 3, sub = t & 7;
        float vals[32];
        #pragma unroll
        for (int k4 = 0; k4 < 8; k4++) {
            float4 v = *(const float4*)&as[r][sub*4 + k4*32];
            vals[k4*4+0] = v.x; vals[k4*4+1] = v.y; vals[k4*4+2] = v.z; vals[k4*4+3] = v.w;
        }
        float sum = 0.f, sq = 0.f;
        #pragma unroll
        for (int k = 0; k < 32; k++) { sum += vals[k]; sq = fmaf(vals[k], vals[k], sq); }
        #pragma unroll
        for (int o = 1; o < 8; o <<= 1) {
            sum += __shfl_xor_sync(0xffffffffu, sum, o);
            sq  += __shfl_xor_sync(0xffffffffu, sq, o);
        }
        const float mean = sum * (1.f / 256.f);
        const float var  = sq * (1.f / 256.f) - mean * mean;
        const float rstd = rsqrtf(var + 1e-3f);

        #pragma unroll
        for (int k4 = 0; k4 < 8; k4++) {
            const int c = sub*4 + k4*32;
            float4 ga = *(const float4*)&gamma[c];
            float4 be = *(const float4*)&beta[c];
            float4 uu = *(const float4*)&g_u[(r0 + r)*256 + c];
            float4 o;
            o.x = tf32f(uu.x * ((vals[k4*4+0] - mean) * rstd * ga.x + be.x));
            o.y = tf32f(uu.y * ((vals[k4*4+1] - mean) * rstd * ga.y + be.y));
            o.z = tf32f(uu.z * ((vals[k4*4+2] - mean) * rstd * ga.z + be.z));
            o.w = tf32f(uu.w * ((vals[k4*4+3] - mean) * rstd * ga.w + be.w));
            *(float4*)&as[r][c] = o;
        }
    }
    __syncthreads();

    // ---- GEMM 32x256 @ Wf[256,128] via tf32 MMA ----
    const int w = t >> 5, lane = t & 31;
    const int wm = w & 1, wn = w >> 1;         // 2m x 4n
    const int g = lane >> 2, tg = lane & 3;
    const int lrow = lane & 7;
    const int sel4 = lane >> 3;
    const int a_ro = ((sel4 & 1) << 3) + lrow;
    const int a_co = (sel4 & 2) ? 4 : 0;

    const uint32 aa = as_u + ((wm*16 + a_ro)*260 + a_co)*4;

    float4 acc[4];
    #pragma unroll
    for (int j = 0; j < 4; j++) acc[j] = make_float4(0.f, 0.f, 0.f, 0.f);

    for (int kc = 0; kc < 256; kc += 32) {
        #pragma unroll
        for (int i = t*4; i < 32*128; i += 256*4) {
            int rr = i >> 7, cc = i & 127;
            float4 v4 = *(const float4*)&Wf[(kc + rr) * 128 + cc];
            ws[rr][cc+0] = tf32f(v4.x); ws[rr][cc+1] = tf32f(v4.y);
            ws[rr][cc+2] = tf32f(v4.z); ws[rr][cc+3] = tf32f(v4.w);
        }
        __syncthreads();

        #pragma unroll
        for (int kk = 0; kk < 32; kk += 8) {
            uint32 A[4];
            ldsm_x4(A[0], A[1], A[2], A[3], aa + (kc + kk)*4);
            #pragma unroll
            for (int j = 0; j < 4; j++) {
                uint32 b0 = fb(ws[kk + tg    ][wn*32 + j*8 + g]);
                uint32 b1 = fb(ws[kk + tg + 4][wn*32 + j*8 + g]);
                mma_tf32(acc[j], A[0], A[1], A[2], A[3], b0, b1);
            }
        }
        __syncthreads();
    }

    // epilogue: +bf, relu, +x
    {
        const int row0 = r0 + wm*16 + g, row1 = row0 + 8;
        #pragma unroll
        for (int j = 0; j < 4; j++) {
            const int col = wn*32 + j*8 + 2*tg;
            float b0v = bf[col], b1v = bf[col + 1];
            float2 x0 = *(const float2*)&x[row0*128 + col];
            float2 x1 = *(const float2*)&x[row1*128 + col];
            float2 o0, o1;
            o0.x = fmaxf(acc[j].x + b0v, 0.f) + x0.x;
            o0.y = fmaxf(acc[j].y + b1v, 0.f) + x0.y;
            o1.x = fmaxf(acc[j].z + b0v, 0.f) + x1.x;
            o1.y = fmaxf(acc[j].w + b1v, 0.f) + x1.y;
            *(float2*)&out[row0*128 + col] = o0;
            *(float2*)&out[row1*128 + col] = o1;
        }
    }
}

// ---------------- launcher ----------------
extern "C" void kernel_launch(void* const* d_in, const int* in_sizes, int n_in,
                              void* d_out, int out_size)
{
    const float* x      = (const float*)d_in[0];
    const float* Wq     = (const float*)d_in[1];
    const float* bq     = (const float*)d_in[2];
    const float* Wk     = (const float*)d_in[3];
    const float* bk     = (const float*)d_in[4];
    const float* Wv     = (const float*)d_in[5];
    const float* bv     = (const float*)d_in[6];
    const float* Wu     = (const float*)d_in[7];
    const float* bu     = (const float*)d_in[8];
    const float* pos_w  = (const float*)d_in[9];
    const float* gamma  = (const float*)d_in[10];
    const float* beta   = (const float*)d_in[11];
    const float* Wf     = (const float*)d_in[12];
    const float* bf     = (const float*)d_in[13];
    float* out = (float*)d_out;

    cudaFuncSetAttribute(attn_kernel,  cudaFuncAttributeMaxDynamicSharedMemorySize, ATTN_SMEM);
    cudaFuncSetAttribute(pos_kernel,   cudaFuncAttributeMaxDynamicSharedMemorySize, POS_SMEM);
    cudaFuncSetAttribute(final_kernel, cudaFuncAttributeMaxDynamicSharedMemorySize, FIN_SMEM);

    proj_kernel<<<dim3(5, ROWS/64), 256>>>(x, Wq, bq, Wk, bk, Wv, bv, Wu, bu);
    attn_kernel<<<dim3(16, BATCH*4), 256, ATTN_SMEM>>>();
    pos_kernel<<<dim3(SEQ/64, 2, BATCH), 256, POS_SMEM>>>(pos_w);
    final_kernel<<<ROWS/32, 256, FIN_SMEM>>>(x, Wf, bf, gamma, beta, out);
}

// round 10
// speedup vs baseline: 1.7786x; 1.0524x over previous
#include <cuda_runtime.h>
#include <math.h>

#define BATCH 4
#define SEQ   2048
#define DIM   128
#define ROWS  (BATCH*SEQ)   // 8192

typedef unsigned long long ull;
typedef unsigned int uint32;

// ---------------- scratch (no allocation allowed) ----------------
__device__ float g_q[ROWS*DIM];       // tf32-rounded, PRE-SCALED by 1/sqrt(32)
__device__ float g_k[ROWS*DIM];       // tf32-rounded
__device__ float g_vt[ROWS*DIM];      // tf32-rounded, TRANSPOSED: [b][d=128][token=2048]
__device__ float g_u[ROWS*2*DIM];     // full f32
__device__ float g_wf[2*DIM*DIM];     // tf32-rounded Wf
__device__ float g_sattn[ROWS*DIM];
__device__ float g_pattn[ROWS*DIM];

__device__ __forceinline__ float silu_f(float v) {
    return v * (1.f / (1.f + __expf(-v)));
}
__device__ __forceinline__ float tanh_ap(float x) {
    float y; asm("tanh.approx.f32 %0, %1;" : "=f"(y) : "f"(x)); return y;
}
// silu via 1 MUFU: x*sigmoid(x) = x*(0.5*tanh(0.5x)+0.5)
__device__ __forceinline__ float silu_t(float x) {
    return fmaf(x, 0.5f * tanh_ap(0.5f * x), 0.5f * x);
}
__device__ __forceinline__ uint32 tf32_of(float f) {
    uint32 u; asm("cvt.rna.tf32.f32 %0, %1;" : "=r"(u) : "f"(f)); return u;
}
__device__ __forceinline__ float tf32f(float f) { return __uint_as_float(tf32_of(f)); }
__device__ __forceinline__ uint32 fb(float f) { return __float_as_uint(f); }
__device__ __forceinline__ uint32 smem_u32(const void* p) {
    return (uint32)__cvta_generic_to_shared(p);
}

__device__ __forceinline__ void mma_tf32(float4& d, uint32 a0, uint32 a1, uint32 a2, uint32 a3,
                                         uint32 b0, uint32 b1) {
    asm volatile(
        "mma.sync.aligned.m16n8k8.row.col.f32.tf32.tf32.f32 "
        "{%0,%1,%2,%3}, {%4,%5,%6,%7}, {%8,%9}, {%0,%1,%2,%3};"
        : "+f"(d.x), "+f"(d.y), "+f"(d.z), "+f"(d.w)
        : "r"(a0), "r"(a1), "r"(a2), "r"(a3), "r"(b0), "r"(b1));
}
__device__ __forceinline__ void ldsm_x4(uint32& r0, uint32& r1, uint32& r2, uint32& r3, uint32 addr) {
    asm volatile("ldmatrix.sync.aligned.m8n8.x4.shared.b16 {%0,%1,%2,%3}, [%4];"
        : "=r"(r0), "=r"(r1), "=r"(r2), "=r"(r3) : "r"(addr));
}
__device__ __forceinline__ void ldsm_x2(uint32& r0, uint32& r1, uint32 addr) {
    asm volatile("ldmatrix.sync.aligned.m8n8.x2.shared.b16 {%0,%1}, [%2];"
        : "=r"(r0), "=r"(r1) : "r"(addr));
}
__device__ __forceinline__ void cp16(uint32 dst, const float* src) {
    asm volatile("cp.async.ca.shared.global [%0], [%1], 16;" :: "r"(dst), "l"(src));
}
#define CP_COMMIT() asm volatile("cp.async.commit_group;")
#define CP_WAIT2()  asm volatile("cp.async.wait_group 2;")
#define CP_WAIT1()  asm volatile("cp.async.wait_group 1;")
#define CP_WAIT0()  asm volatile("cp.async.wait_group 0;")

// ---------------- kernel 1: fused q/k/v/u projections (tf32 mma) ----------------
// grid (6, 128). seg 0=q(pre-scaled), 1=k, 2=v(transposed), 3/4=u halves, 5=Wf tf32 copy.
__global__ __launch_bounds__(256) void proj_kernel(
    const float* __restrict__ x,
    const float* __restrict__ Wq, const float* __restrict__ bq,
    const float* __restrict__ Wk, const float* __restrict__ bk,
    const float* __restrict__ Wv, const float* __restrict__ bv,
    const float* __restrict__ Wu, const float* __restrict__ bu,
    const float* __restrict__ Wf)
{
    __shared__ float xs[64][36];
    __shared__ float ws[32][136];

    const int seg = blockIdx.x;
    const int r0  = blockIdx.y * 64;

    if (seg == 5) {
        // tf32-round Wf: 32768 floats over 128 blocks -> 64 float4 per block
        const int t = threadIdx.x;
        if (t < 64) {
            int i4 = blockIdx.y * 64 + t;
            float4 v = *(const float4*)&Wf[i4 * 4];
            float4 o = make_float4(tf32f(v.x), tf32f(v.y), tf32f(v.z), tf32f(v.w));
            *(float4*)&g_wf[i4 * 4] = o;
        }
        return;
    }

    const float* W; const float* bias; int ldw, c0;
    if (seg == 0)      { W = Wq; bias = bq; ldw = 128; c0 = 0; }
    else if (seg == 1) { W = Wk; bias = bk; ldw = 128; c0 = 0; }
    else if (seg == 2) { W = Wv; bias = bv; ldw = 128; c0 = 0; }
    else               { W = Wu; bias = bu; ldw = 256; c0 = (seg - 3) * 128; }

    const int t = threadIdx.x;
    const int w = t >> 5, lane = t & 31;
    const int wm = w & 3, wn = w >> 2;
    const int g = lane >> 2, tg = lane & 3;

    float4 acc[8];
    #pragma unroll
    for (int j = 0; j < 8; j++) acc[j] = make_float4(0.f, 0.f, 0.f, 0.f);

    for (int kc = 0; kc < 128; kc += 32) {
        #pragma unroll
        for (int i = t*4; i < 64*32; i += 256*4) {
            int rr = i >> 5, cc = i & 31;
            float4 v4 = *(const float4*)&x[(r0 + rr) * 128 + kc + cc];
            xs[rr][cc+0] = tf32f(v4.x); xs[rr][cc+1] = tf32f(v4.y);
            xs[rr][cc+2] = tf32f(v4.z); xs[rr][cc+3] = tf32f(v4.w);
        }
        #pragma unroll
        for (int i = t*4; i < 32*128; i += 256*4) {
            int rr = i >> 7, cc = i & 127;
            float4 v4 = *(const float4*)&W[(kc + rr) * ldw + c0 + cc];
            ws[rr][cc+0] = tf32f(v4.x); ws[rr][cc+1] = tf32f(v4.y);
            ws[rr][cc+2] = tf32f(v4.z); ws[rr][cc+3] = tf32f(v4.w);
        }
        __syncthreads();

        #pragma unroll
        for (int kk = 0; kk < 32; kk += 8) {
            uint32 a0 = fb(xs[wm*16 + g    ][kk + tg    ]);
            uint32 a1 = fb(xs[wm*16 + g + 8][kk + tg    ]);
            uint32 a2 = fb(xs[wm*16 + g    ][kk + tg + 4]);
            uint32 a3 = fb(xs[wm*16 + g + 8][kk + tg + 4]);
            #pragma unroll
            for (int j = 0; j < 8; j++) {
                uint32 b0 = fb(ws[kk + tg    ][wn*64 + j*8 + g]);
                uint32 b1 = fb(ws[kk + tg + 4][wn*64 + j*8 + g]);
                mma_tf32(acc[j], a0, a1, a2, a3, b0, b1);
            }
        }
        __syncthreads();
    }

    if (seg == 2) {
        const int bb = r0 >> 11;
        const int tok = (r0 & 2047) + wm*16 + g;
        #pragma unroll
        for (int j = 0; j < 8; j++) {
            int col = wn*64 + j*8 + 2*tg;
            float b0v = bias[col], b1v = bias[col + 1];
            float v00 = tf32f(silu_f(acc[j].x + b0v));
            float v01 = tf32f(silu_f(acc[j].y + b1v));
            float v10 = tf32f(silu_f(acc[j].z + b0v));
            float v11 = tf32f(silu_f(acc[j].w + b1v));
            float* p0 = &g_vt[(bb*128 + col) * SEQ + tok];
            p0[0] = v00; p0[8] = v10;
            float* p1 = p0 + SEQ;
            p1[0] = v01; p1[8] = v11;
        }
    } else {
        float* out = (seg == 0) ? g_q : (seg == 1) ? g_k : g_u;
        bool act = (seg <= 1);
        const float mult = (seg == 0) ? 0.17677669529663687f : 1.0f;
        #pragma unroll
        for (int j = 0; j < 8; j++) {
            int col = c0 + wn*64 + j*8 + 2*tg;
            float b0v = bias[col], b1v = bias[col + 1];
            int row0 = r0 + wm*16 + g;
            float v00 = acc[j].x + b0v, v01 = acc[j].y + b1v;
            float v10 = acc[j].z + b0v, v11 = acc[j].w + b1v;
            if (act) {
                v00 = tf32f(silu_f(v00) * mult); v01 = tf32f(silu_f(v01) * mult);
                v10 = tf32f(silu_f(v10) * mult); v11 = tf32f(silu_f(v11) * mult);
            }
            *(float2*)&out[row0 * ldw + col]       = make_float2(v00, v01);
            *(float2*)&out[(row0 + 8) * ldw + col] = make_float2(v10, v11);
        }
    }
}

// ---------------- kernel 2: MERGED attn + pos ----------------
// grid 512, 256 threads, 62464 B dyn smem. Even blocks = attn, odd = pos.
#define AP_SMEM 62464

__device__ __forceinline__ void attn_body(int p, int bh, int t, float* sm)
{
    float (*qs)[36]  = (float(*)[36])sm;                 // 64 rows
    float (*ks)[36]  = (float(*)[36])(sm + 2304);        // 2*64 rows
    float (*vts)[68] = (float(*)[68])(sm + 6912);        // 2*32 rows
    float (*ss)[68]  = (float(*)[68])(sm + 11264);       // 64 rows

    const int b = bh >> 2, h = bh & 3;
    const int w = t >> 5, lane = t & 31;
    const int wm = w & 3, wn = w >> 2;
    const int g = lane >> 2, tg = lane & 3;

    const float* kp  = g_k  + (b*SEQ)*128 + h*32;
    const float* vtp = g_vt + (b*128 + h*32)*SEQ;

    const uint32 qs_u = smem_u32(&qs[0][0]);
    const uint32 ks_u = smem_u32(&ks[0][0]);
    const uint32 vt_u = smem_u32(&vts[0][0]);
    const uint32 ss_u = smem_u32(&ss[0][0]);

    const int lrow = lane & 7;
    const int sel4 = lane >> 3;
    const int a_ro = ((sel4 & 1) << 3) + lrow;
    const int a_co = (sel4 & 2) ? 4 : 0;
    const int l16  = lane & 15;
    const int b_ro = l16 & 7;
    const int b_co = (l16 >> 3) << 2;

    const uint32 qa = qs_u + ((wm*16 + a_ro)*36 + a_co)*4;
    const uint32 sa = ss_u + ((wm*16 + a_ro)*68 + a_co)*4;

    #pragma unroll
    for (int ph = 0; ph < 2; ph++) {
        const int tile = ph ? p : 31 - p;        // long phase first
        const int n0 = tile * 64;
        const float* qp = g_q + (b*SEQ + n0)*128 + h*32;

        #pragma unroll
        for (int c = t; c < 512; c += 256) {
            int r = c >> 3, s = (c & 7) << 2;
            cp16(qs_u + (r*36 + s)*4, qp + r*128 + s);
        }
        #pragma unroll
        for (int c = t; c < 512; c += 256) {
            int r = c >> 3, s = (c & 7) << 2;
            cp16(ks_u + (r*36 + s)*4, kp + r*128 + s);
        }
        #pragma unroll
        for (int c = t; c < 512; c += 256) {
            int r = c >> 4, s = (c & 15) << 2;
            cp16(vt_u + (r*68 + s)*4, vtp + r*SEQ + s);
        }
        CP_COMMIT();

        float4 acc2[2];
        acc2[0] = make_float4(0.f, 0.f, 0.f, 0.f);
        acc2[1] = make_float4(0.f, 0.f, 0.f, 0.f);

        const int iters = tile + 1;
        for (int it = 0; it < iters; ++it) {
            const int m0 = it * 64;
            const int buf = it & 1;
            if (it + 1 < iters) {
                const int m1 = m0 + 64, nb = buf ^ 1;
                #pragma unroll
                for (int c = t; c < 512; c += 256) {
                    int r = c >> 3, s = (c & 7) << 2;
                    cp16(ks_u + ((nb*64 + r)*36 + s)*4, kp + (m1 + r)*128 + s);
                }
                #pragma unroll
                for (int c = t; c < 512; c += 256) {
                    int r = c >> 4, s = (c & 15) << 2;
                    cp16(vt_u + ((nb*32 + r)*68 + s)*4, vtp + r*SEQ + m1 + s);
                }
                CP_COMMIT();
                CP_WAIT1();
            } else {
                CP_WAIT0();
            }
            __syncthreads();

            // stage 1: scores 64x64 (warp m16 x n32)
            float4 sc[4];
            #pragma unroll
            for (int j = 0; j < 4; j++) sc[j] = make_float4(0.f, 0.f, 0.f, 0.f);

            const uint32 kb = ks_u + (uint32)buf*64*36*4 + ((wn*32 + b_ro)*36 + b_co)*4;
            #pragma unroll
            for (int kk = 0; kk < 32; kk += 8) {
                uint32 A[4];
                ldsm_x4(A[0], A[1], A[2], A[3], qa + kk*4);
                #pragma unroll
                for (int j = 0; j < 4; j++) {
                    uint32 b0, b1;
                    ldsm_x2(b0, b1, kb + (j*8*36 + kk)*4);
                    mma_tf32(sc[j], A[0], A[1], A[2], A[3], b0, b1);
                }
            }

            // mask + square + silu(tanh) -> ss (tf32)
            {
                const int lr = wm*16 + g;
                const int nrow0 = n0 + lr, nrow1 = nrow0 + 8;
                #pragma unroll
                for (int j = 0; j < 4; j++) {
                    const int lc = wn*32 + j*8 + 2*tg;
                    const int cc = m0 + lc;
                    float s;
                    s = sc[j].x; s = (cc     <= nrow0) ? s*s : 0.f; float w00 = tf32f(silu_t(s));
                    s = sc[j].y; s = (cc + 1 <= nrow0) ? s*s : 0.f; float w01 = tf32f(silu_t(s));
                    s = sc[j].z; s = (cc     <= nrow1) ? s*s : 0.f; float w10 = tf32f(silu_t(s));
                    s = sc[j].w; s = (cc + 1 <= nrow1) ? s*s : 0.f; float w11 = tf32f(silu_t(s));
                    *(float2*)&ss[lr    ][lc] = make_float2(w00, w01);
                    *(float2*)&ss[lr + 8][lc] = make_float2(w10, w11);
                }
            }
            __syncthreads();

            // stage 2: acc2 += ss @ v  (warp m16 x d16)
            const uint32 vb = vt_u + (uint32)buf*32*68*4 + ((wn*16 + b_ro)*68 + b_co)*4;
            #pragma unroll
            for (int kk = 0; kk < 64; kk += 8) {
                uint32 A[4];
                ldsm_x4(A[0], A[1], A[2], A[3], sa + kk*4);
                #pragma unroll
                for (int j = 0; j < 2; j++) {
                    uint32 b0, b1;
                    ldsm_x2(b0, b1, vb + (j*8*68 + kk)*4);
                    mma_tf32(acc2[j], A[0], A[1], A[2], A[3], b0, b1);
                }
            }
            __syncthreads();
        }

        {
            const int row0 = n0 + wm*16 + g;
            #pragma unroll
            for (int j = 0; j < 2; j++) {
                const int col = h*32 + wn*16 + j*8 + 2*tg;
                *(float2*)&g_sattn[(b*SEQ + row0    )*128 + col] = make_float2(acc2[j].x, acc2[j].y);
                *(float2*)&g_sattn[(b*SEQ + row0 + 8)*128 + col] = make_float2(acc2[j].z, acc2[j].w);
            }
        }
    }
}

__device__ __forceinline__ void pos_body(int idx, int t, float* sm, const float* __restrict__ pos_w)
{
    float* swl = sm;                                   // 4096 (tf32-rounded pos_w)
    float (*vts)[68] = (float(*)[68])(sm + 4096);      // 2*64 rows

    const int n0 = (idx & 31) * 64;
    const int d0 = ((idx >> 5) & 1) * 64;
    const int b  = idx >> 6;
    const int w = t >> 5, lane = t & 31;
    const int wmn = w & 1, wd = w >> 1;
    const int g = lane >> 2, tg = lane & 3;

    const int l16  = lane & 15;
    const int b_ro = l16 & 7;
    const int b_co = (l16 >> 3) << 2;

    const uint32 vt_u = smem_u32(&vts[0][0]);
    const float* vtp = g_vt + (b*128 + d0)*SEQ;

    for (int i = t; i < 4095; i += 256) swl[i] = tf32f(pos_w[i]);
    if (t == 0) swl[4095] = 0.f;

    #pragma unroll
    for (int c = t; c < 1024; c += 256) {
        int r = c >> 4, s = (c & 15) << 2;
        cp16(vt_u + (r*68 + s)*4, vtp + r*SEQ + s);
    }
    CP_COMMIT();

    float4 acc[2][2];
    #pragma unroll
    for (int mi = 0; mi < 2; mi++)
        #pragma unroll
        for (int j = 0; j < 2; j++) acc[mi][j] = make_float4(0.f, 0.f, 0.f, 0.f);

    const int abase = 2047 - n0 - wmn*32 - g + tg;

    for (int it = 0; it < 32; ++it) {
        const int m0 = it * 64;
        const int buf = it & 1;
        if (it < 31) {
            const int m1 = m0 + 64, nb = buf ^ 1;
            #pragma unroll
            for (int c = t; c < 1024; c += 256) {
                int r = c >> 4, s = (c & 15) << 2;
                cp16(vt_u + ((nb*64 + r)*68 + s)*4, vtp + r*SEQ + m1 + s);
            }
            CP_COMMIT();
            CP_WAIT1();
        } else {
            CP_WAIT0();
        }
        __syncthreads();

        const uint32 vb = vt_u + (uint32)buf*64*68*4 + ((wd*16 + b_ro)*68 + b_co)*4;
        const float* ab = swl + abase + m0;
        #pragma unroll
        for (int kk = 0; kk < 64; kk += 8) {
            uint32 A0[4], A1[4];
            {
                const float* pp = ab + kk;
                A0[0] = fb(pp[0]);   A0[1] = fb(pp[-8]);
                A0[2] = fb(pp[4]);   A0[3] = fb(pp[-4]);
                const float* qq = pp - 16;
                A1[0] = fb(qq[0]);   A1[1] = fb(qq[-8]);
                A1[2] = fb(qq[4]);   A1[3] = fb(qq[-4]);
            }
            #pragma unroll
            for (int j = 0; j < 2; j++) {
                uint32 b0, b1;
                ldsm_x2(b0, b1, vb + (j*8*68 + kk)*4);
                mma_tf32(acc[0][j], A0[0], A0[1], A0[2], A0[3], b0, b1);
                mma_tf32(acc[1][j], A1[0], A1[1], A1[2], A1[3], b0, b1);
            }
        }
        __syncthreads();
    }

    #pragma unroll
    for (int mi = 0; mi < 2; mi++) {
        const int row0 = n0 + wmn*32 + mi*16 + g;
        #pragma unroll
        for (int j = 0; j < 2; j++) {
            const int col = d0 + wd*16 + j*8 + 2*tg;
            *(float2*)&g_pattn[(b*SEQ + row0    )*128 + col] = make_float2(acc[mi][j].x, acc[mi][j].y);
            *(float2*)&g_pattn[(b*SEQ + row0 + 8)*128 + col] = make_float2(acc[mi][j].z, acc[mi][j].w);
        }
    }
}

__global__ __launch_bounds__(256, 3) void attnpos_kernel(const float* __restrict__ pos_w)
{
    extern __shared__ float sm[];
    const int bx = blockIdx.x;
    const int idx = bx >> 1;
    if ((bx & 1) == 0) {
        attn_body(idx & 15, idx >> 4, threadIdx.x, sm);
    } else {
        pos_body(idx, threadIdx.x, sm, pos_w);
    }
}

// ---------------- kernel 3: fused LN + final GEMM (tf32 mma, pipelined Wf) ----------------
// grid 256, 256 threads = 8 warps (2m x 4n), warp m16 x n32. Block: 32 rows x 128 cols.
// smem: as[32][260] (33280 B) + ws[2][32][132] (33792 B) = 67072 B
#define FIN_SMEM 67072
__global__ __launch_bounds__(256) void final_kernel(const float* __restrict__ x,
                                                    const float* __restrict__ bf,
                                                    const float* __restrict__ gamma,
                                                    const float* __restrict__ beta,
                                                    float* __restrict__ out)
{
    extern __shared__ float sm[];
    float (*as)[260] = (float(*)[260])sm;            // 32 rows, cols 0..255 = [sattn|pattn]
    float (*ws)[132] = (float(*)[132])(sm + 32*260); // 2 x 32 rows

    const int r0 = blockIdx.x * 32;
    const int t  = threadIdx.x;
    const uint32 as_u = smem_u32(&as[0][0]);
    const uint32 ws_u = smem_u32(&ws[0][0]);

    // group 0: activations (32 rows x 256 floats = 2048 float4)
    #pragma unroll
    for (int i = t; i < 2048; i += 256) {
        int r = i >> 6, c4 = i & 63;
        const float* src = (c4 < 32) ? &g_sattn[(r0 + r)*128 + c4*4]
                                     : &g_pattn[(r0 + r)*128 + (c4 - 32)*4];
        cp16(as_u + (r*260 + c4*4)*4, src);
    }
    CP_COMMIT();
    // groups 1,2: Wf chunks 0,1 (each 32 rows x 128 floats = 1024 float4 -> 4/thread)
    #pragma unroll
    for (int i = t; i < 1024; i += 256) {
        int r = i >> 5, c4 = i & 31;
        cp16(ws_u + (r*132 + c4*4)*4, &g_wf[r*128 + c4*4]);
    }
    CP_COMMIT();
    #pragma unroll
    for (int i = t; i < 1024; i += 256) {
        int r = i >> 5, c4 = i & 31;
        cp16(ws_u + ((32 + r)*132 + c4*4)*4, &g_wf[(32 + r)*128 + c4*4]);
    }
    CP_COMMIT();
    CP_WAIT2();   // activations ready
    __syncthreads();

    // ---- LayerNorm: 8 threads/row; thread covers cols {sub*4 + k4*32}
    {
        const int r = t >> 3, sub = t & 7;
        float vals[32];
        #pragma unroll
        for (int k4 = 0; k4 < 8; k4++) {
            float4 v = *(const float4*)&as[r][sub*4 + k4*32];
            vals[k4*4+0] = v.x; vals[k4*4+1] = v.y; vals[k4*4+2] = v.z; vals[k4*4+3] = v.w;
        }
        float sum = 0.f, sq = 0.f;
        #pragma unroll
        for (int k = 0; k < 32; k++) { sum += vals[k]; sq = fmaf(vals[k], vals[k], sq); }
        #pragma unroll
        for (int o = 1; o < 8; o <<= 1) {
            sum += __shfl_xor_sync(0xffffffffu, sum, o);
            sq  += __shfl_xor_sync(0xffffffffu, sq, o);
        }
        const float mean = sum * (1.f / 256.f);
        const float var  = sq * (1.f / 256.f) - mean * mean;
        const float rstd = rsqrtf(var + 1e-3f);

        #pragma unroll
        for (int k4 = 0; k4 < 8; k4++) {
            const int c = sub*4 + k4*32;
            float4 ga = *(const float4*)&gamma[c];
            float4 be = *(const float4*)&beta[c];
            float4 uu = *(const float4*)&g_u[(r0 + r)*256 + c];
            float4 o;
            o.x = tf32f(uu.x * ((vals[k4*4+0] - mean) * rstd * ga.x + be.x));
            o.y = tf32f(uu.y * ((vals[k4*4+1] - mean) * rstd * ga.y + be.y));
            o.z = tf32f(uu.z * ((vals[k4*4+2] - mean) * rstd * ga.z + be.z));
            o.w = tf32f(uu.w * ((vals[k4*4+3] - mean) * rstd * ga.w + be.w));
            *(float4*)&as[r][c] = o;
        }
    }
    __syncthreads();

    // ---- GEMM 32x256 @ Wf[256,128] via tf32 MMA, Wf double-buffered ----
    const int w = t >> 5, lane = t & 31;
    const int wm = w & 1, wn = w >> 1;         // 2m x 4n
    const int g = lane >> 2, tg = lane & 3;
    const int lrow = lane & 7;
    const int sel4 = lane >> 3;
    const int a_ro = ((sel4 & 1) << 3) + lrow;
    const int a_co = (sel4 & 2) ? 4 : 0;

    const uint32 aa = as_u + ((wm*16 + a_ro)*260 + a_co)*4;

    float4 acc[4];
    #pragma unroll
    for (int j = 0; j < 4; j++) acc[j] = make_float4(0.f, 0.f, 0.f, 0.f);

    #pragma unroll
    for (int kchunk = 0; kchunk < 8; kchunk++) {
        const int buf = kchunk & 1;
        CP_WAIT1();     // chunk `kchunk` resident
        __syncthreads();

        #pragma unroll
        for (int kk = 0; kk < 32; kk += 8) {
            uint32 A[4];
            ldsm_x4(A[0], A[1], A[2], A[3], aa + (kchunk*32 + kk)*4);
            #pragma unroll
            for (int j = 0; j < 4; j++) {
                uint32 b0 = fb(ws[buf*32 + kk + tg    ][wn*32 + j*8 + g]);
                uint32 b1 = fb(ws[buf*32 + kk + tg + 4][wn*32 + j*8 + g]);
                mma_tf32(acc[j], A[0], A[1], A[2], A[3], b0, b1);
            }
        }
        __syncthreads();

        if (kchunk + 2 < 8) {
            #pragma unroll
            for (int i = t; i < 1024; i += 256) {
                int r = i >> 5, c4 = i & 31;
                cp16(ws_u + ((buf*32 + r)*132 + c4*4)*4,
                     &g_wf[((kchunk + 2)*32 + r)*128 + c4*4]);
            }
        }
        CP_COMMIT();    // commit every iter (possibly empty) to keep group counting uniform
    }

    // epilogue: +bf, relu, +x
    {
        const int row0 = r0 + wm*16 + g, row1 = row0 + 8;
        #pragma unroll
        for (int j = 0; j < 4; j++) {
            const int col = wn*32 + j*8 + 2*tg;
            float b0v = bf[col], b1v = bf[col + 1];
            float2 x0 = *(const float2*)&x[row0*128 + col];
            float2 x1 = *(const float2*)&x[row1*128 + col];
            float2 o0, o1;
            o0.x = fmaxf(acc[j].x + b0v, 0.f) + x0.x;
            o0.y = fmaxf(acc[j].y + b1v, 0.f) + x0.y;
            o1.x = fmaxf(acc[j].z + b0v, 0.f) + x1.x;
            o1.y = fmaxf(acc[j].w + b1v, 0.f) + x1.y;
            *(float2*)&out[row0*128 + col] = o0;
            *(float2*)&out[row1*128 + col] = o1;
        }
    }
}

// ---------------- launcher ----------------
extern "C" void kernel_launch(void* const* d_in, const int* in_sizes, int n_in,
                              void* d_out, int out_size)
{
    const float* x      = (const float*)d_in[0];
    const float* Wq     = (const float*)d_in[1];
    const float* bq     = (const float*)d_in[2];
    const float* Wk     = (const float*)d_in[3];
    const float* bk     = (const float*)d_in[4];
    const float* Wv     = (const float*)d_in[5];
    const float* bv     = (const float*)d_in[6];
    const float* Wu     = (const float*)d_in[7];
    const float* bu     = (const float*)d_in[8];
    const float* pos_w  = (const float*)d_in[9];
    const float* gamma  = (const float*)d_in[10];
    const float* beta   = (const float*)d_in[11];
    const float* Wf     = (const float*)d_in[12];
    const float* bf     = (const float*)d_in[13];
    float* out = (float*)d_out;

    cudaFuncSetAttribute(attnpos_kernel, cudaFuncAttributeMaxDynamicSharedMemorySize, AP_SMEM);
    cudaFuncSetAttribute(final_kernel,   cudaFuncAttributeMaxDynamicSharedMemorySize, FIN_SMEM);

    proj_kernel<<<dim3(6, ROWS/64), 256>>>(x, Wq, bq, Wk, bk, Wv, bv, Wu, bu, Wf);
    attnpos_kernel<<<512, 256, AP_SMEM>>>(pos_w);
    final_kernel<<<ROWS/32, 256, FIN_SMEM>>>(x, bf, gamma, beta, out);
}

// round 11
// speedup vs baseline: 1.8072x; 1.0161x over previous
#include <cuda_runtime.h>
#include <math.h>

#define BATCH 4
#define SEQ   2048
#define DIM   128
#define ROWS  (BATCH*SEQ)   // 8192

typedef unsigned long long ull;
typedef unsigned int uint32;

// ---------------- scratch (no allocation allowed) ----------------
__device__ float g_q[ROWS*DIM];       // tf32-rounded, PRE-SCALED by 1/sqrt(32)
__device__ float g_k[ROWS*DIM];       // tf32-rounded
__device__ float g_vt[ROWS*DIM];      // tf32-rounded, TRANSPOSED: [b][d=128][token=2048]
__device__ float g_u[ROWS*2*DIM];     // full f32
__device__ float g_wf[2*DIM*DIM];     // tf32-rounded Wf
__device__ float g_sattn[ROWS*DIM];
__device__ float g_pattn[ROWS*DIM];

__device__ __forceinline__ float silu_f(float v) {
    return v * (1.f / (1.f + __expf(-v)));
}
__device__ __forceinline__ float tanh_ap(float x) {
    float y; asm("tanh.approx.f32 %0, %1;" : "=f"(y) : "f"(x)); return y;
}
// silu via 1 MUFU: x*sigmoid(x) = x*(0.5*tanh(0.5x)+0.5)
__device__ __forceinline__ float silu_t(float x) {
    return fmaf(x, 0.5f * tanh_ap(0.5f * x), 0.5f * x);
}
__device__ __forceinline__ uint32 tf32_of(float f) {
    uint32 u; asm("cvt.rna.tf32.f32 %0, %1;" : "=r"(u) : "f"(f)); return u;
}
__device__ __forceinline__ float tf32f(float f) { return __uint_as_float(tf32_of(f)); }
__device__ __forceinline__ uint32 fb(float f) { return __float_as_uint(f); }
__device__ __forceinline__ uint32 smem_u32(const void* p) {
    return (uint32)__cvta_generic_to_shared(p);
}

__device__ __forceinline__ void mma_tf32(float4& d, uint32 a0, uint32 a1, uint32 a2, uint32 a3,
                                         uint32 b0, uint32 b1) {
    asm volatile(
        "mma.sync.aligned.m16n8k8.row.col.f32.tf32.tf32.f32 "
        "{%0,%1,%2,%3}, {%4,%5,%6,%7}, {%8,%9}, {%0,%1,%2,%3};"
        : "+f"(d.x), "+f"(d.y), "+f"(d.z), "+f"(d.w)
        : "r"(a0), "r"(a1), "r"(a2), "r"(a3), "r"(b0), "r"(b1));
}
__device__ __forceinline__ void ldsm_x4(uint32& r0, uint32& r1, uint32& r2, uint32& r3, uint32 addr) {
    asm volatile("ldmatrix.sync.aligned.m8n8.x4.shared.b16 {%0,%1,%2,%3}, [%4];"
        : "=r"(r0), "=r"(r1), "=r"(r2), "=r"(r3) : "r"(addr));
}
__device__ __forceinline__ void ldsm_x2(uint32& r0, uint32& r1, uint32 addr) {
    asm volatile("ldmatrix.sync.aligned.m8n8.x2.shared.b16 {%0,%1}, [%2];"
        : "=r"(r0), "=r"(r1) : "r"(addr));
}
__device__ __forceinline__ void cp16(uint32 dst, const float* src) {
    asm volatile("cp.async.ca.shared.global [%0], [%1], 16;" :: "r"(dst), "l"(src));
}
#define CP_COMMIT() asm volatile("cp.async.commit_group;")
#define CP_WAIT2()  asm volatile("cp.async.wait_group 2;")
#define CP_WAIT1()  asm volatile("cp.async.wait_group 1;")
#define CP_WAIT0()  asm volatile("cp.async.wait_group 0;")

// ---------------- kernel 1: fused q/k/v/u projections (tf32 mma, cp.async pipeline) ----------------
// grid (6, 128). seg 0=q(pre-scaled), 1=k, 2=v(transposed), 3/4=u halves, 5=Wf tf32 copy.
// Raw fp32 staged via cp.async; tf32 MMA truncates inputs (rz). Outputs tf32-rounded (rna).
// dyn smem: xs 2*64*36 (18432 B) + ws 2*32*136 (34816 B) = 53248 B
#define PROJ_SMEM 53248
__global__ __launch_bounds__(256) void proj_kernel(
    const float* __restrict__ x,
    const float* __restrict__ Wq, const float* __restrict__ bq,
    const float* __restrict__ Wk, const float* __restrict__ bk,
    const float* __restrict__ Wv, const float* __restrict__ bv,
    const float* __restrict__ Wu, const float* __restrict__ bu,
    const float* __restrict__ Wf)
{
    extern __shared__ float psm[];
    float (*xs)[36]  = (float(*)[36])psm;                 // 2 x 64 rows
    float (*ws)[136] = (float(*)[136])(psm + 2*64*36);    // 2 x 32 rows

    const int seg = blockIdx.x;
    const int r0  = blockIdx.y * 64;

    if (seg == 5) {
        // tf32-round Wf: 32768 floats over 128 blocks -> 64 float4 per block
        const int t = threadIdx.x;
        if (t < 64) {
            int i4 = blockIdx.y * 64 + t;
            float4 v = *(const float4*)&Wf[i4 * 4];
            float4 o = make_float4(tf32f(v.x), tf32f(v.y), tf32f(v.z), tf32f(v.w));
            *(float4*)&g_wf[i4 * 4] = o;
        }
        return;
    }

    const float* W; const float* bias; int ldw, c0;
    if (seg == 0)      { W = Wq; bias = bq; ldw = 128; c0 = 0; }
    else if (seg == 1) { W = Wk; bias = bk; ldw = 128; c0 = 0; }
    else if (seg == 2) { W = Wv; bias = bv; ldw = 128; c0 = 0; }
    else               { W = Wu; bias = bu; ldw = 256; c0 = (seg - 3) * 128; }

    const int t = threadIdx.x;
    const int w = t >> 5, lane = t & 31;
    const int wm = w & 3, wn = w >> 2;
    const int g = lane >> 2, tg = lane & 3;

    // ldmatrix lane-address components (A fragment)
    const int lrow = lane & 7;
    const int sel4 = lane >> 3;
    const int a_ro = ((sel4 & 1) << 3) + lrow;
    const int a_co = (sel4 & 2) ? 4 : 0;

    const uint32 xs_u = smem_u32(&xs[0][0]);
    const uint32 ws_u = smem_u32(&ws[0][0]);
    const float* xp = x + r0 * 128;

    // preload chunk 0 (x cols 0..31, W rows 0..31)
    #pragma unroll
    for (int i = t; i < 512; i += 256) {
        int r = i >> 3, q = (i & 7) << 2;
        cp16(xs_u + (r*36 + q)*4, xp + r*128 + q);
    }
    #pragma unroll
    for (int i = t; i < 1024; i += 256) {
        int r = i >> 5, q = (i & 31) << 2;
        cp16(ws_u + (r*136 + q)*4, W + r*ldw + c0 + q);
    }
    CP_COMMIT();

    float4 acc[8];
    #pragma unroll
    for (int j = 0; j < 8; j++) acc[j] = make_float4(0.f, 0.f, 0.f, 0.f);

    const uint32 xa = xs_u + ((wm*16 + a_ro)*36 + a_co)*4;

    #pragma unroll
    for (int kc = 0; kc < 4; kc++) {
        const int buf = kc & 1;
        if (kc < 3) {
            const int nb = buf ^ 1, k1 = (kc + 1) * 32;
            #pragma unroll
            for (int i = t; i < 512; i += 256) {
                int r = i >> 3, q = (i & 7) << 2;
                cp16(xs_u + ((nb*64 + r)*36 + q)*4, xp + r*128 + k1 + q);
            }
            #pragma unroll
            for (int i = t; i < 1024; i += 256) {
                int r = i >> 5, q = (i & 31) << 2;
                cp16(ws_u + ((nb*32 + r)*136 + q)*4, W + (k1 + r)*ldw + c0 + q);
            }
            CP_COMMIT();
            CP_WAIT1();
        } else {
            CP_WAIT0();
        }
        __syncthreads();

        const uint32 xab = xa + (uint32)buf*64*36*4;
        #pragma unroll
        for (int kk = 0; kk < 32; kk += 8) {
            uint32 A[4];
            ldsm_x4(A[0], A[1], A[2], A[3], xab + kk*4);
            #pragma unroll
            for (int j = 0; j < 8; j++) {
                uint32 b0 = fb(ws[buf*32 + kk + tg    ][wn*64 + j*8 + g]);
                uint32 b1 = fb(ws[buf*32 + kk + tg + 4][wn*64 + j*8 + g]);
                mma_tf32(acc[j], A[0], A[1], A[2], A[3], b0, b1);
            }
        }
        __syncthreads();
    }

    if (seg == 2) {
        const int bb = r0 >> 11;
        const int tok = (r0 & 2047) + wm*16 + g;
        #pragma unroll
        for (int j = 0; j < 8; j++) {
            int col = wn*64 + j*8 + 2*tg;
            float b0v = bias[col], b1v = bias[col + 1];
            float v00 = tf32f(silu_f(acc[j].x + b0v));
            float v01 = tf32f(silu_f(acc[j].y + b1v));
            float v10 = tf32f(silu_f(acc[j].z + b0v));
            float v11 = tf32f(silu_f(acc[j].w + b1v));
            float* p0 = &g_vt[(bb*128 + col) * SEQ + tok];
            p0[0] = v00; p0[8] = v10;
            float* p1 = p0 + SEQ;
            p1[0] = v01; p1[8] = v11;
        }
    } else {
        float* out = (seg == 0) ? g_q : (seg == 1) ? g_k : g_u;
        bool act = (seg <= 1);
        const float mult = (seg == 0) ? 0.17677669529663687f : 1.0f;
        #pragma unroll
        for (int j = 0; j < 8; j++) {
            int col = c0 + wn*64 + j*8 + 2*tg;
            float b0v = bias[col], b1v = bias[col + 1];
            int row0 = r0 + wm*16 + g;
            float v00 = acc[j].x + b0v, v01 = acc[j].y + b1v;
            float v10 = acc[j].z + b0v, v11 = acc[j].w + b1v;
            if (act) {
                v00 = tf32f(silu_f(v00) * mult); v01 = tf32f(silu_f(v01) * mult);
                v10 = tf32f(silu_f(v10) * mult); v11 = tf32f(silu_f(v11) * mult);
            }
            *(float2*)&out[row0 * ldw + col]       = make_float2(v00, v01);
            *(float2*)&out[(row0 + 8) * ldw + col] = make_float2(v10, v11);
        }
    }
}

// ---------------- kernel 2: MERGED attn + pos ----------------
// grid 512, 256 threads, 62464 B dyn smem. Even blocks = attn, odd = pos.
#define AP_SMEM 62464

__device__ __forceinline__ void attn_body(int p, int bh, int t, float* sm)
{
    float (*qs)[36]  = (float(*)[36])sm;                 // 64 rows
    float (*ks)[36]  = (float(*)[36])(sm + 2304);        // 2*64 rows
    float (*vts)[68] = (float(*)[68])(sm + 6912);        // 2*32 rows
    float (*ss)[68]  = (float(*)[68])(sm + 11264);       // 64 rows

    const int b = bh >> 2, h = bh & 3;
    const int w = t >> 5, lane = t & 31;
    const int wm = w & 3, wn = w >> 2;
    const int g = lane >> 2, tg = lane & 3;

    const float* kp  = g_k  + (b*SEQ)*128 + h*32;
    const float* vtp = g_vt + (b*128 + h*32)*SEQ;

    const uint32 qs_u = smem_u32(&qs[0][0]);
    const uint32 ks_u = smem_u32(&ks[0][0]);
    const uint32 vt_u = smem_u32(&vts[0][0]);
    const uint32 ss_u = smem_u32(&ss[0][0]);

    const int lrow = lane & 7;
    const int sel4 = lane >> 3;
    const int a_ro = ((sel4 & 1) << 3) + lrow;
    const int a_co = (sel4 & 2) ? 4 : 0;
    const int l16  = lane & 15;
    const int b_ro = l16 & 7;
    const int b_co = (l16 >> 3) << 2;

    const uint32 qa = qs_u + ((wm*16 + a_ro)*36 + a_co)*4;
    const uint32 sa = ss_u + ((wm*16 + a_ro)*68 + a_co)*4;

    #pragma unroll
    for (int ph = 0; ph < 2; ph++) {
        const int tile = ph ? p : 31 - p;        // long phase first
        const int n0 = tile * 64;
        const float* qp = g_q + (b*SEQ + n0)*128 + h*32;

        #pragma unroll
        for (int c = t; c < 512; c += 256) {
            int r = c >> 3, s = (c & 7) << 2;
            cp16(qs_u + (r*36 + s)*4, qp + r*128 + s);
        }
        #pragma unroll
        for (int c = t; c < 512; c += 256) {
            int r = c >> 3, s = (c & 7) << 2;
            cp16(ks_u + (r*36 + s)*4, kp + r*128 + s);
        }
        #pragma unroll
        for (int c = t; c < 512; c += 256) {
            int r = c >> 4, s = (c & 15) << 2;
            cp16(vt_u + (r*68 + s)*4, vtp + r*SEQ + s);
        }
        CP_COMMIT();

        float4 acc2[2];
        acc2[0] = make_float4(0.f, 0.f, 0.f, 0.f);
        acc2[1] = make_float4(0.f, 0.f, 0.f, 0.f);

        const int iters = tile + 1;
        for (int it = 0; it < iters; ++it) {
            const int m0 = it * 64;
            const int buf = it & 1;
            if (it + 1 < iters) {
                const int m1 = m0 + 64, nb = buf ^ 1;
                #pragma unroll
                for (int c = t; c < 512; c += 256) {
                    int r = c >> 3, s = (c & 7) << 2;
                    cp16(ks_u + ((nb*64 + r)*36 + s)*4, kp + (m1 + r)*128 + s);
                }
                #pragma unroll
                for (int c = t; c < 512; c += 256) {
                    int r = c >> 4, s = (c & 15) << 2;
                    cp16(vt_u + ((nb*32 + r)*68 + s)*4, vtp + r*SEQ + m1 + s);
                }
                CP_COMMIT();
                CP_WAIT1();
            } else {
                CP_WAIT0();
            }
            __syncthreads();

            // stage 1: scores 64x64 (warp m16 x n32)
            float4 sc[4];
            #pragma unroll
            for (int j = 0; j < 4; j++) sc[j] = make_float4(0.f, 0.f, 0.f, 0.f);

            const uint32 kb = ks_u + (uint32)buf*64*36*4 + ((wn*32 + b_ro)*36 + b_co)*4;
            #pragma unroll
            for (int kk = 0; kk < 32; kk += 8) {
                uint32 A[4];
                ldsm_x4(A[0], A[1], A[2], A[3], qa + kk*4);
                #pragma unroll
                for (int j = 0; j < 4; j++) {
                    uint32 b0, b1;
                    ldsm_x2(b0, b1, kb + (j*8*36 + kk)*4);
                    mma_tf32(sc[j], A[0], A[1], A[2], A[3], b0, b1);
                }
            }

            // mask + square + silu(tanh) -> ss (tf32)
            {
                const int lr = wm*16 + g;
                const int nrow0 = n0 + lr, nrow1 = nrow0 + 8;
                #pragma unroll
                for (int j = 0; j < 4; j++) {
                    const int lc = wn*32 + j*8 + 2*tg;
                    const int cc = m0 + lc;
                    float s;
                    s = sc[j].x; s = (cc     <= nrow0) ? s*s : 0.f; float w00 = tf32f(silu_t(s));
                    s = sc[j].y; s = (cc + 1 <= nrow0) ? s*s : 0.f; float w01 = tf32f(silu_t(s));
                    s = sc[j].z; s = (cc     <= nrow1) ? s*s : 0.f; float w10 = tf32f(silu_t(s));
                    s = sc[j].w; s = (cc + 1 <= nrow1) ? s*s : 0.f; float w11 = tf32f(silu_t(s));
                    *(float2*)&ss[lr    ][lc] = make_float2(w00, w01);
                    *(float2*)&ss[lr + 8][lc] = make_float2(w10, w11);
                }
            }
            __syncthreads();

            // stage 2: acc2 += ss @ v  (warp m16 x d16)
            const uint32 vb = vt_u + (uint32)buf*32*68*4 + ((wn*16 + b_ro)*68 + b_co)*4;
            #pragma unroll
            for (int kk = 0; kk < 64; kk += 8) {
                uint32 A[4];
                ldsm_x4(A[0], A[1], A[2], A[3], sa + kk*4);
                #pragma unroll
                for (int j = 0; j < 2; j++) {
                    uint32 b0, b1;
                    ldsm_x2(b0, b1, vb + (j*8*68 + kk)*4);
                    mma_tf32(acc2[j], A[0], A[1], A[2], A[3], b0, b1);
                }
            }
            __syncthreads();
        }

        {
            const int row0 = n0 + wm*16 + g;
            #pragma unroll
            for (int j = 0; j < 2; j++) {
                const int col = h*32 + wn*16 + j*8 + 2*tg;
                *(float2*)&g_sattn[(b*SEQ + row0    )*128 + col] = make_float2(acc2[j].x, acc2[j].y);
                *(float2*)&g_sattn[(b*SEQ + row0 + 8)*128 + col] = make_float2(acc2[j].z, acc2[j].w);
            }
        }
    }
}

__device__ __forceinline__ void pos_body(int idx, int t, float* sm, const float* __restrict__ pos_w)
{
    float* swl = sm;                                   // 4096 (tf32-rounded pos_w)
    float (*vts)[68] = (float(*)[68])(sm + 4096);      // 2*64 rows

    const int n0 = (idx & 31) * 64;
    const int d0 = ((idx >> 5) & 1) * 64;
    const int b  = idx >> 6;
    const int w = t >> 5, lane = t & 31;
    const int wmn = w & 1, wd = w >> 1;
    const int g = lane >> 2, tg = lane & 3;

    const int l16  = lane & 15;
    const int b_ro = l16 & 7;
    const int b_co = (l16 >> 3) << 2;

    const uint32 vt_u = smem_u32(&vts[0][0]);
    const float* vtp = g_vt + (b*128 + d0)*SEQ;

    for (int i = t; i < 4095; i += 256) swl[i] = tf32f(pos_w[i]);
    if (t == 0) swl[4095] = 0.f;

    #pragma unroll
    for (int c = t; c < 1024; c += 256) {
        int r = c >> 4, s = (c & 15) << 2;
        cp16(vt_u + (r*68 + s)*4, vtp + r*SEQ + s);
    }
    CP_COMMIT();

    float4 acc[2][2];
    #pragma unroll
    for (int mi = 0; mi < 2; mi++)
        #pragma unroll
        for (int j = 0; j < 2; j++) acc[mi][j] = make_float4(0.f, 0.f, 0.f, 0.f);

    const int abase = 2047 - n0 - wmn*32 - g + tg;

    for (int it = 0; it < 32; ++it) {
        const int m0 = it * 64;
        const int buf = it & 1;
        if (it < 31) {
            const int m1 = m0 + 64, nb = buf ^ 1;
            #pragma unroll
            for (int c = t; c < 1024; c += 256) {
                int r = c >> 4, s = (c & 15) << 2;
                cp16(vt_u + ((nb*64 + r)*68 + s)*4, vtp + r*SEQ + m1 + s);
            }
            CP_COMMIT();
            CP_WAIT1();
        } else {
            CP_WAIT0();
        }
        __syncthreads();

        const uint32 vb = vt_u + (uint32)buf*64*68*4 + ((wd*16 + b_ro)*68 + b_co)*4;
        const float* ab = swl + abase + m0;
        #pragma unroll
        for (int kk = 0; kk < 64; kk += 8) {
            uint32 A0[4], A1[4];
            {
                const float* pp = ab + kk;
                A0[0] = fb(pp[0]);   A0[1] = fb(pp[-8]);
                A0[2] = fb(pp[4]);   A0[3] = fb(pp[-4]);
                const float* qq = pp - 16;
                A1[0] = fb(qq[0]);   A1[1] = fb(qq[-8]);
                A1[2] = fb(qq[4]);   A1[3] = fb(qq[-4]);
            }
            #pragma unroll
            for (int j = 0; j < 2; j++) {
                uint32 b0, b1;
                ldsm_x2(b0, b1, vb + (j*8*68 + kk)*4);
                mma_tf32(acc[0][j], A0[0], A0[1], A0[2], A0[3], b0, b1);
                mma_tf32(acc[1][j], A1[0], A1[1], A1[2], A1[3], b0, b1);
            }
        }
        __syncthreads();
    }

    #pragma unroll
    for (int mi = 0; mi < 2; mi++) {
        const int row0 = n0 + wmn*32 + mi*16 + g;
        #pragma unroll
        for (int j = 0; j < 2; j++) {
            const int col = d0 + wd*16 + j*8 + 2*tg;
            *(float2*)&g_pattn[(b*SEQ + row0    )*128 + col] = make_float2(acc[mi][j].x, acc[mi][j].y);
            *(float2*)&g_pattn[(b*SEQ + row0 + 8)*128 + col] = make_float2(acc[mi][j].z, acc[mi][j].w);
        }
    }
}

__global__ __launch_bounds__(256, 3) void attnpos_kernel(const float* __restrict__ pos_w)
{
    extern __shared__ float sm[];
    const int bx = blockIdx.x;
    const int idx = bx >> 1;
    if ((bx & 1) == 0) {
        attn_body(idx & 15, idx >> 4, threadIdx.x, sm);
    } else {
        pos_body(idx, threadIdx.x, sm, pos_w);
    }
}

// ---------------- kernel 3: fused LN + final GEMM (tf32 mma, pipelined Wf) ----------------
// grid 256, 256 threads = 8 warps (2m x 4n), warp m16 x n32. Block: 32 rows x 128 cols.
// smem: as[32][260] (33280 B) + ws[2][32][132] (33792 B) = 67072 B
#define FIN_SMEM 67072
__global__ __launch_bounds__(256) void final_kernel(const float* __restrict__ x,
                                                    const float* __restrict__ bf,
                                                    const float* __restrict__ gamma,
                                                    const float* __restrict__ beta,
                                                    float* __restrict__ out)
{
    extern __shared__ float sm[];
    float (*as)[260] = (float(*)[260])sm;            // 32 rows, cols 0..255 = [sattn|pattn]
    float (*ws)[132] = (float(*)[132])(sm + 32*260); // 2 x 32 rows

    const int r0 = blockIdx.x * 32;
    const int t  = threadIdx.x;
    const uint32 as_u = smem_u32(&as[0][0]);
    const uint32 ws_u = smem_u32(&ws[0][0]);

    // group 0: activations (32 rows x 256 floats = 2048 float4)
    #pragma unroll
    for (int i = t; i < 2048; i += 256) {
        int r = i >> 6, c4 = i & 63;
        const float* src = (c4 < 32) ? &g_sattn[(r0 + r)*128 + c4*4]
                                     : &g_pattn[(r0 + r)*128 + (c4 - 32)*4];
        cp16(as_u + (r*260 + c4*4)*4, src);
    }
    CP_COMMIT();
    // groups 1,2: Wf chunks 0,1 (each 32 rows x 128 floats = 1024 float4 -> 4/thread)
    #pragma unroll
    for (int i = t; i < 1024; i += 256) {
        int r = i >> 5, c4 = i & 31;
        cp16(ws_u + (r*132 + c4*4)*4, &g_wf[r*128 + c4*4]);
    }
    CP_COMMIT();
    #pragma unroll
    for (int i = t; i < 1024; i += 256) {
        int r = i >> 5, c4 = i & 31;
        cp16(ws_u + ((32 + r)*132 + c4*4)*4, &g_wf[(32 + r)*128 + c4*4]);
    }
    CP_COMMIT();
    CP_WAIT2();   // activations ready
    __syncthreads();

    // ---- LayerNorm: 8 threads/row; thread covers cols {sub*4 + k4*32}
    {
        const int r = t >> 3, sub = t & 7;
        float vals[32];
        #pragma unroll
        for (int k4 = 0; k4 < 8; k4++) {
            float4 v = *(const float4*)&as[r][sub*4 + k4*32];
            vals[k4*4+0] = v.x; vals[k4*4+1] = v.y; vals[k4*4+2] = v.z; vals[k4*4+3] = v.w;
        }
        float sum = 0.f, sq = 0.f;
        #pragma unroll
        for (int k = 0; k < 32; k++) { sum += vals[k]; sq = fmaf(vals[k], vals[k], sq); }
        #pragma unroll
        for (int o = 1; o < 8; o <<= 1) {
            sum += __shfl_xor_sync(0xffffffffu, sum, o);
            sq  += __shfl_xor_sync(0xffffffffu, sq, o);
        }
        const float mean = sum * (1.f / 256.f);
        const float var  = sq * (1.f / 256.f) - mean * mean;
        const float rstd = rsqrtf(var + 1e-3f);

        #pragma unroll
        for (int k4 = 0; k4 < 8; k4++) {
            const int c = sub*4 + k4*32;
            float4 ga = *(const float4*)&gamma[c];
            float4 be = *(const float4*)&beta[c];
            float4 uu = *(const float4*)&g_u[(r0 + r)*256 + c];
            float4 o;
            o.x = tf32f(uu.x * ((vals[k4*4+0] - mean) * rstd * ga.x + be.x));
            o.y = tf32f(uu.y * ((vals[k4*4+1] - mean) * rstd * ga.y + be.y));
            o.z = tf32f(uu.z * ((vals[k4*4+2] - mean) * rstd * ga.z + be.z));
            o.w = tf32f(uu.w * ((vals[k4*4+3] - mean) * rstd * ga.w + be.w));
            *(float4*)&as[r][c] = o;
        }
    }
    __syncthreads();

    // ---- GEMM 32x256 @ Wf[256,128] via tf32 MMA, Wf double-buffered ----
    const int w = t >> 5, lane = t & 31;
    const int wm = w & 1, wn = w >> 1;         // 2m x 4n
    const int g = lane >> 2, tg = lane & 3;
    const int lrow = lane & 7;
    const int sel4 = lane >> 3;
    const int a_ro = ((sel4 & 1) << 3) + lrow;
    const int a_co = (sel4 & 2) ? 4 : 0;

    const uint32 aa = as_u + ((wm*16 + a_ro)*260 + a_co)*4;

    float4 acc[4];
    #pragma unroll
    for (int j = 0; j < 4; j++) acc[j] = make_float4(0.f, 0.f, 0.f, 0.f);

    #pragma unroll
    for (int kchunk = 0; kchunk < 8; kchunk++) {
        const int buf = kchunk & 1;
        CP_WAIT1();     // chunk `kchunk` resident
        __syncthreads();

        #pragma unroll
        for (int kk = 0; kk < 32; kk += 8) {
            uint32 A[4];
            ldsm_x4(A[0], A[1], A[2], A[3], aa + (kchunk*32 + kk)*4);
            #pragma unroll
            for (int j = 0; j < 4; j++) {
                uint32 b0 = fb(ws[buf*32 + kk + tg    ][wn*32 + j*8 + g]);
                uint32 b1 = fb(ws[buf*32 + kk + tg + 4][wn*32 + j*8 + g]);
                mma_tf32(acc[j], A[0], A[1], A[2], A[3], b0, b1);
            }
        }
        __syncthreads();

        if (kchunk + 2 < 8) {
            #pragma unroll
            for (int i = t; i < 1024; i += 256) {
                int r = i >> 5, c4 = i & 31;
                cp16(ws_u + ((buf*32 + r)*132 + c4*4)*4,
                     &g_wf[((kchunk + 2)*32 + r)*128 + c4*4]);
            }
        }
        CP_COMMIT();    // commit every iter (possibly empty) to keep group counting uniform
    }

    // epilogue: +bf, relu, +x
    {
        const int row0 = r0 + wm*16 + g, row1 = row0 + 8;
        #pragma unroll
        for (int j = 0; j < 4; j++) {
            const int col = wn*32 + j*8 + 2*tg;
            float b0v = bf[col], b1v = bf[col + 1];
            float2 x0 = *(const float2*)&x[row0*128 + col];
            float2 x1 = *(const float2*)&x[row1*128 + col];
            float2 o0, o1;
            o0.x = fmaxf(acc[j].x + b0v, 0.f) + x0.x;
            o0.y = fmaxf(acc[j].y + b1v, 0.f) + x0.y;
            o1.x = fmaxf(acc[j].z + b0v, 0.f) + x1.x;
            o1.y = fmaxf(acc[j].w + b1v, 0.f) + x1.y;
            *(float2*)&out[row0*128 + col] = o0;
            *(float2*)&out[row1*128 + col] = o1;
        }
    }
}

// ---------------- launcher ----------------
extern "C" void kernel_launch(void* const* d_in, const int* in_sizes, int n_in,
                              void* d_out, int out_size)
{
    const float* x      = (const float*)d_in[0];
    const float* Wq     = (const float*)d_in[1];
    const float* bq     = (const float*)d_in[2];
    const float* Wk     = (const float*)d_in[3];
    const float* bk     = (const float*)d_in[4];
    const float* Wv     = (const float*)d_in[5];
    const float* bv     = (const float*)d_in[6];
    const float* Wu     = (const float*)d_in[7];
    const float* bu     = (const float*)d_in[8];
    const float* pos_w  = (const float*)d_in[9];
    const float* gamma  = (const float*)d_in[10];
    const float* beta   = (const float*)d_in[11];
    const float* Wf     = (const float*)d_in[12];
    const float* bf     = (const float*)d_in[13];
    float* out = (float*)d_out;

    cudaFuncSetAttribute(proj_kernel,    cudaFuncAttributeMaxDynamicSharedMemorySize, PROJ_SMEM);
    cudaFuncSetAttribute(attnpos_kernel, cudaFuncAttributeMaxDynamicSharedMemorySize, AP_SMEM);
    cudaFuncSetAttribute(final_kernel,   cudaFuncAttributeMaxDynamicSharedMemorySize, FIN_SMEM);

    proj_kernel<<<dim3(6, ROWS/64), 256, PROJ_SMEM>>>(x, Wq, bq, Wk, bk, Wv, bv, Wu, bu, Wf);
    attnpos_kernel<<<512, 256, AP_SMEM>>>(pos_w);
    final_kernel<<<ROWS/32, 256, FIN_SMEM>>>(x, bf, gamma, beta, out);
}